// round 5
// baseline (speedup 1.0000x reference)
#include <cuda_runtime.h>
#include <cuda_bf16.h>

// Problem constants (fixed by dataset)
#define BB 2
#define CC 256
#define HH 56
#define WW 56
#define NN 64
#define MM 8
#define PP 7
#define R_PER_IMG (NN + NN*MM)        // 576
#define R_TOTAL   (BB * R_PER_IMG)    // 1152
#define MAXK 12

// Per-roi tables.
// g_meta[r*16 + row], row 0..6 = y rows (p), 7..13 = x rows (q). meta = off | (cnt<<8)
// g_yinfo[r] = ylo | (span4<<8)   (span4 = y-support span rounded up to 4)
// g_wgt[(r*14+row)*12 + k], zero-padded to 12 floats per row, 16B aligned
__device__ int   g_meta[R_TOTAL * 16];
__device__ int   g_yinfo[R_TOTAL];
__device__ __align__(16) float g_wgt[R_TOTAL * 14 * MAXK];

// ---------------------------------------------------------------------------
// Kernel A: build sparse interpolation tables for every roi & axis.
// One thread per (roi, axis). Replicates reference math exactly.
// ---------------------------------------------------------------------------
__global__ void prep_kernel(const float* __restrict__ boxes,
                            const float* __restrict__ gts) {
    int t = blockIdx.x * blockDim.x + threadIdx.x;
    if (t >= R_TOTAL * 2) return;
    int r = t >> 1, a = t & 1;
    int b = r / R_PER_IMG, idx = r % R_PER_IMG;

    float x1, y1, x2, y2;
    if (idx < NN) {
        const float* bx = boxes + (b * NN + idx) * 4;
        x1 = bx[0]; y1 = bx[1]; x2 = bx[2]; y2 = bx[3];
    } else {
        int n = (idx - NN) >> 3, m = (idx - NN) & 7;
        const float* bx = boxes + (b * NN + n) * 4;
        const float* gx = gts   + (b * MM + m) * 4;
        x1 = fminf(bx[0], gx[0]); y1 = fminf(bx[1], gx[1]);
        x2 = fmaxf(bx[2], gx[2]); y2 = fmaxf(bx[3], gx[3]);
    }

    float start = a ? x1 : y1;
    float len   = fmaxf(a ? (x2 - x1) : (y2 - y1), 1.0f);
    const float dimf = 56.0f;
    const int   dim  = 56;

    float bin = len / 7.0f;
    int   g   = (int)ceilf(bin);           // grid = ceil(length/P)
    float gf  = (float)g;
    float inv = 1.0f / gf;

    int lo_min = 1 << 20, hi_max = -1;
    for (int p = 0; p < 7; p++) {
        float acc[MAXK];
        #pragma unroll
        for (int k = 0; k < MAXK; k++) acc[k] = 0.0f;
        int base = -1, hi = -1;
        float c0 = start + (float)p * bin;
        for (int s = 0; s < 8; s++) {
            if (s >= g) break;
            float coord = c0 + ((float)s + 0.5f) * bin / gf;
            if (!(coord >= -1.0f && coord <= dimf)) continue;
            float c = fmaxf(coord, 0.0f);
            int low = (int)floorf(c);
            int high; float cv;
            if (low >= dim - 1) { low = dim - 1; high = dim - 1; cv = (float)low; }
            else                { high = low + 1; cv = c; }
            float l  = cv - (float)low;
            float wl = (1.0f - l) * inv;
            float wh = l * inv;
            if (base < 0) base = low;
            int d  = low  - base;
            int d2 = high - base;
            if (d  >= 0 && d  < MAXK) acc[d]  += wl;
            if (d2 >= 0 && d2 < MAXK) acc[d2] += wh;
            if (high > hi) hi = high;
        }
        int cnt = (base < 0) ? 0 : (hi - base + 1);
        if (base < 0) base = 0;
        if (cnt > MAXK) cnt = MAXK;   // safety (true bound is 10)
        if (base < lo_min) lo_min = base;
        if (base + cnt > hi_max) hi_max = base + cnt;
        g_meta[r * 16 + a * 7 + p] = base | (cnt << 8);
        float* wp = g_wgt + (size_t)((r * 14 + a * 7 + p)) * MAXK;
        #pragma unroll
        for (int k = 0; k < MAXK; k++) wp[k] = acc[k];
    }
    if (a == 0) {
        int lo = lo_min, span = hi_max - lo_min;
        if (span < 1) { lo = 0; span = 1; }
        int span4 = (span + 3) & ~3;
        g_yinfo[r] = lo | (span4 << 8);
    }
}

// ---------------------------------------------------------------------------
// Kernel B: main compute. One CTA per (channel-pair, image, n-sixteenth).
// fm for 2 channels interleaved in smem (68-col row stride, zero-padded;
// stride 68 puts the 4 h-subgroups on distinct bank quadrants).
// 16 warps, one n each. Per n: box roi + 8 ctx rois.
// Stage 1 (x-interp): lanes 0..27 -> (hsub = lane/7, q = lane%7); group-of-2
//   k chain with per-lane predicates -> near-exact bytes. Weights in regs,
//   loaded conditionally (w1 iff cnt>4, w2 iff cnt>8).
// Stage 2 (y-interp): lane -> output cell(s), stride-7 tmp reads, same
//   group-of-2 predicated chain.
// ---------------------------------------------------------------------------
#define FSTRIDE 68

// group-of-2 for stage 1: two float2 fm reads, two weights
#define S1P(wa, wb, k0) { \
    float2 f0 = cc[(k0)], f1 = cc[(k0)+1]; \
    a.x += wa * f0.x + wb * f1.x; \
    a.y += wa * f0.y + wb * f1.y; }

// group-of-2 for stage 2: two stride-7 tmp reads, two weights
#define S2P(wa, wb, k0) { \
    float2 t0 = tp[(k0)*7], t1 = tp[((k0)+1)*7]; \
    s.x += wa * t0.x + wb * t1.x; \
    s.y += wa * t0.y + wb * t1.y; }

__global__ void __launch_bounds__(512, 2)
roi_main_kernel(const float* __restrict__ fm, float* __restrict__ out) {
    const int cp = blockIdx.x;          // channel pair: c0 = 2*cp
    const int b  = blockIdx.y;
    const int nbase = blockIdx.z * 16;  // 16 n per CTA, one per warp

    __shared__ float2 fm_s[64 * FSTRIDE];       // 34816 B, fully initialized
    __shared__ float2 tmp_s[16][64 * 7];        // 57344 B

    const int tid = threadIdx.x;
    const int c0 = cp * 2;

    // ---- stage fm[b][c0..c0+1] interleaved; zero all padding + tmp ----
    {
        const float2 z2 = make_float2(0.f, 0.f);
        // zero rows 56..63 fully, and cols 56..67 of rows 0..55
        for (int i = tid; i < 8 * FSTRIDE; i += 512) fm_s[56 * FSTRIDE + i] = z2;
        for (int i = tid; i < 56 * 12; i += 512) {
            int h = i / 12, w = 56 + (i % 12);
            fm_s[h * FSTRIDE + w] = z2;
        }
        // zero tmp (stage-2 over-reads must stay finite for first roi)
        float2* tz = &tmp_s[0][0];
        for (int i = tid; i < 16 * 64 * 7; i += 512) tz[i] = z2;

        const float4* s0 = (const float4*)(fm + ((size_t)(b * CC + c0)     ) * (HH * WW));
        const float4* s1 = (const float4*)(fm + ((size_t)(b * CC + c0 + 1)) * (HH * WW));
        for (int i = tid; i < 784; i += 512) {       // 784 float4 per channel
            float4 v0 = s0[i];
            float4 v1 = s1[i];
            int h = i / 14, w = (i % 14) * 4;
            float2* d = &fm_s[h * FSTRIDE + w];
            d[0] = make_float2(v0.x, v1.x);
            d[1] = make_float2(v0.y, v1.y);
            d[2] = make_float2(v0.z, v1.z);
            d[3] = make_float2(v0.w, v1.w);
        }
    }
    __syncthreads();

    const int wid  = tid >> 5;
    const int lane = tid & 31;
    float2* tmpw = tmp_s[wid];

    // stage-1 lane mapping: lanes 0..27 -> (hsub, qx)
    const int qx   = lane % 7;
    const int hsub = lane / 7;
    const bool act1 = (lane < 28);

    // stage-2 cell mapping: cell0 = lane, cell1 = lane+32
    const int p0 = lane / 7,        q0 = lane % 7;
    const int p1 = (lane + 32) / 7, q1 = (lane + 32) % 7;
    const bool has1 = (lane + 32 < 49);

    const int n = nbase + wid;

    float2 acc0 = make_float2(0.f, 0.f);
    float2 acc1 = make_float2(0.f, 0.f);

    #pragma unroll 1
    for (int j = 0; j < 9; j++) {
        const int r = b * R_PER_IMG + ((j == 0) ? n : (NN + n * 8 + (j - 1)));
        const float wroi = (j == 0) ? 1.0f : 0.125f;
        const int yinfo = __ldg(&g_yinfo[r]);
        const int ylo   = yinfo & 0xFF;
        const int span4 = yinfo >> 8;
        const int mbase = r * 16;
        const float* wbase = g_wgt + (size_t)r * 168;

        // ---- stage 1: x-interp. tmp[h][q] = sum_k wX[q][k]*fm[ylo+h][offx_q+k]
        {
            int metax = __ldg(&g_meta[mbase + 7 + qx]);
            int offx = metax & 0xFF, cntx = metax >> 8;
            const float4* wx4 = (const float4*)(wbase + (7 + qx) * 12);
            float4 wx0 = __ldg(wx4);
            float4 wx1 = make_float4(0.f, 0.f, 0.f, 0.f);
            float4 wx2 = make_float4(0.f, 0.f, 0.f, 0.f);
            if (cntx > 4) wx1 = __ldg(wx4 + 1);
            if (cntx > 8) wx2 = __ldg(wx4 + 2);
            #pragma unroll 1
            for (int hb = 0; hb < span4; hb += 4) {
                if (act1) {
                    int h = hb + hsub;
                    const float2* cc = fm_s + (ylo + h) * FSTRIDE + offx;
                    float2 a = make_float2(0.f, 0.f);
                    S1P(wx0.x, wx0.y, 0);
                    if (cntx >  2) { S1P(wx0.z, wx0.w, 2);
                    if (cntx >  4) { S1P(wx1.x, wx1.y, 4);
                    if (cntx >  6) { S1P(wx1.z, wx1.w, 6);
                    if (cntx >  8) { S1P(wx2.x, wx2.y, 8);
                    if (cntx > 10) { S1P(wx2.z, wx2.w, 10); }}}}}
                    tmpw[h * 7 + qx] = a;
                }
            }
        }
        __syncwarp();

        // ---- stage 2: y-interp. out[p][q] = sum_k wY[p][k]*tmp[offy_p-ylo+k][q]
        {
            int metay = __ldg(&g_meta[mbase + p0]);
            int offy = metay & 0xFF, cnty = metay >> 8;
            const float4* wy4 = (const float4*)(wbase + p0 * 12);
            float4 u0 = __ldg(wy4);
            float4 u1 = make_float4(0.f, 0.f, 0.f, 0.f);
            float4 u2 = make_float4(0.f, 0.f, 0.f, 0.f);
            if (cnty > 4) u1 = __ldg(wy4 + 1);
            if (cnty > 8) u2 = __ldg(wy4 + 2);
            const float2* tp = tmpw + (offy - ylo) * 7 + q0;
            float2 s = make_float2(0.f, 0.f);
            S2P(u0.x, u0.y, 0);
            if (cnty >  2) { S2P(u0.z, u0.w, 2);
            if (cnty >  4) { S2P(u1.x, u1.y, 4);
            if (cnty >  6) { S2P(u1.z, u1.w, 6);
            if (cnty >  8) { S2P(u2.x, u2.y, 8);
            if (cnty > 10) { S2P(u2.z, u2.w, 10); }}}}}
            acc0.x += wroi * s.x; acc0.y += wroi * s.y;
        }
        if (has1) {
            int metay = __ldg(&g_meta[mbase + p1]);
            int offy = metay & 0xFF, cnty = metay >> 8;
            const float4* wy4 = (const float4*)(wbase + p1 * 12);
            float4 u0 = __ldg(wy4);
            float4 u1 = make_float4(0.f, 0.f, 0.f, 0.f);
            float4 u2 = make_float4(0.f, 0.f, 0.f, 0.f);
            if (cnty > 4) u1 = __ldg(wy4 + 1);
            if (cnty > 8) u2 = __ldg(wy4 + 2);
            const float2* tp = tmpw + (offy - ylo) * 7 + q1;
            float2 s = make_float2(0.f, 0.f);
            S2P(u0.x, u0.y, 0);
            if (cnty >  2) { S2P(u0.z, u0.w, 2);
            if (cnty >  4) { S2P(u1.x, u1.y, 4);
            if (cnty >  6) { S2P(u1.z, u1.w, 6);
            if (cnty >  8) { S2P(u2.x, u2.y, 8);
            if (cnty > 10) { S2P(u2.z, u2.w, 10); }}}}}
            acc1.x += wroi * s.x; acc1.y += wroi * s.y;
        }
        __syncwarp();   // tmp reuse safety before next roi
    }

    // ---- store out[b][n][c][p][q], channels c0 and c0+1 ----
    float* o = out + ((size_t)(b * NN + n) * CC + c0) * (PP * PP);
    o[lane]      = acc0.x;
    o[49 + lane] = acc0.y;
    if (has1) {
        o[lane + 32]      = acc1.x;
        o[49 + lane + 32] = acc1.y;
    }
}

// ---------------------------------------------------------------------------
extern "C" void kernel_launch(void* const* d_in, const int* in_sizes, int n_in,
                              void* d_out, int out_size) {
    const float* fm    = (const float*)d_in[0];
    const float* boxes = (const float*)d_in[1];
    const float* gts   = (const float*)d_in[2];
    float* out = (float*)d_out;

    prep_kernel<<<(R_TOTAL * 2 + 127) / 128, 128>>>(boxes, gts);

    dim3 grid(CC / 2, BB, 4);
    roi_main_kernel<<<grid, 512>>>(fm, out);
}

// round 6
// speedup vs baseline: 1.0236x; 1.0236x over previous
#include <cuda_runtime.h>
#include <cuda_bf16.h>

// Problem constants (fixed by dataset)
#define BB 2
#define CC 256
#define HH 56
#define WW 56
#define NN 64
#define MM 8
#define PP 7
#define R_PER_IMG (NN + NN*MM)        // 576
#define R_TOTAL   (BB * R_PER_IMG)    // 1152
#define MAXK 12

// Per-roi tables.
// g_meta[r*16 + row], row 0..6 = y rows (p), 7..13 = x rows (q). meta = off | (cnt<<8)
// g_yinfo[r] = ylo | (span4<<8)
// g_kmax[r*2 + a] = warp-uniform max cnt for axis a, rounded up to mult of 4 (4/8/12)
// g_wgt[(r*14+row)*12 + k], zero-padded to 12 floats per row, 16B aligned
__device__ int   g_meta[R_TOTAL * 16];
__device__ int   g_yinfo[R_TOTAL];
__device__ int   g_kmax[R_TOTAL * 2];
__device__ __align__(16) float g_wgt[R_TOTAL * 14 * MAXK];

// ---------------------------------------------------------------------------
// Kernel A: build sparse interpolation tables for every roi & axis.
// One thread per (roi, axis). Replicates reference math exactly.
// ---------------------------------------------------------------------------
__global__ void prep_kernel(const float* __restrict__ boxes,
                            const float* __restrict__ gts) {
    int t = blockIdx.x * blockDim.x + threadIdx.x;
    if (t >= R_TOTAL * 2) return;
    int r = t >> 1, a = t & 1;
    int b = r / R_PER_IMG, idx = r % R_PER_IMG;

    float x1, y1, x2, y2;
    if (idx < NN) {
        const float* bx = boxes + (b * NN + idx) * 4;
        x1 = bx[0]; y1 = bx[1]; x2 = bx[2]; y2 = bx[3];
    } else {
        int n = (idx - NN) >> 3, m = (idx - NN) & 7;
        const float* bx = boxes + (b * NN + n) * 4;
        const float* gx = gts   + (b * MM + m) * 4;
        x1 = fminf(bx[0], gx[0]); y1 = fminf(bx[1], gx[1]);
        x2 = fmaxf(bx[2], gx[2]); y2 = fmaxf(bx[3], gx[3]);
    }

    float start = a ? x1 : y1;
    float len   = fmaxf(a ? (x2 - x1) : (y2 - y1), 1.0f);
    const float dimf = 56.0f;
    const int   dim  = 56;

    float bin = len / 7.0f;
    int   g   = (int)ceilf(bin);           // grid = ceil(length/P)
    float gf  = (float)g;
    float inv = 1.0f / gf;

    int lo_min = 1 << 20, hi_max = -1, cnt_max = 1;
    for (int p = 0; p < 7; p++) {
        float acc[MAXK];
        #pragma unroll
        for (int k = 0; k < MAXK; k++) acc[k] = 0.0f;
        int base = -1, hi = -1;
        float c0 = start + (float)p * bin;
        for (int s = 0; s < 8; s++) {
            if (s >= g) break;
            float coord = c0 + ((float)s + 0.5f) * bin / gf;
            if (!(coord >= -1.0f && coord <= dimf)) continue;
            float c = fmaxf(coord, 0.0f);
            int low = (int)floorf(c);
            int high; float cv;
            if (low >= dim - 1) { low = dim - 1; high = dim - 1; cv = (float)low; }
            else                { high = low + 1; cv = c; }
            float l  = cv - (float)low;
            float wl = (1.0f - l) * inv;
            float wh = l * inv;
            if (base < 0) base = low;
            int d  = low  - base;
            int d2 = high - base;
            if (d  >= 0 && d  < MAXK) acc[d]  += wl;
            if (d2 >= 0 && d2 < MAXK) acc[d2] += wh;
            if (high > hi) hi = high;
        }
        int cnt = (base < 0) ? 0 : (hi - base + 1);
        if (base < 0) base = 0;
        if (cnt > MAXK) cnt = MAXK;   // safety (true bound is 10)
        if (base < lo_min) lo_min = base;
        if (base + cnt > hi_max) hi_max = base + cnt;
        if (cnt > cnt_max) cnt_max = cnt;
        g_meta[r * 16 + a * 7 + p] = base | (cnt << 8);
        float* wp = g_wgt + (size_t)((r * 14 + a * 7 + p)) * MAXK;
        #pragma unroll
        for (int k = 0; k < MAXK; k++) wp[k] = acc[k];
    }
    int km = (cnt_max + 3) & ~3;          // 4, 8 or 12
    if (km < 4)  km = 4;
    if (km > 12) km = 12;
    g_kmax[r * 2 + a] = km;
    if (a == 0) {
        int lo = lo_min, span = hi_max - lo_min;
        if (span < 1) { lo = 0; span = 1; }
        int span4 = (span + 3) & ~3;
        g_yinfo[r] = lo | (span4 << 8);
    }
}

// ---------------------------------------------------------------------------
// Kernel B: main compute. One CTA per (channel-pair, image, n-sixteenth).
// fm for 2 channels interleaved in smem (68-col row stride, zero-padded).
// 16 warps, one n each. Per n: box roi + 8 ctx rois.
// Stage 1 (x-interp): lanes 0..27 -> (hsub = lane/7, q = lane%7). Inner loop
//   selected ONCE per roi from 3 branch-free variants via warp-uniform kmax_x;
//   loads batch fully (MLP 4..12). Zero-padded weights make the per-lane
//   over-read exact.
// Stage 2 (y-interp): lane -> output cell(s), stride-7 tmp reads, same
//   uniform-kmax branch-free unroll.
// ---------------------------------------------------------------------------
#define FSTRIDE 68
#define TROWS   68

// group-of-4 for stage 1: four float2 fm reads, one float4 weight
#define S1G(W, k0) { \
    float2 f0 = cc[(k0)], f1 = cc[(k0)+1], f2 = cc[(k0)+2], f3 = cc[(k0)+3]; \
    a.x += W.x * f0.x + W.y * f1.x + W.z * f2.x + W.w * f3.x; \
    a.y += W.x * f0.y + W.y * f1.y + W.z * f2.y + W.w * f3.y; }

// group-of-4 for stage 2: four stride-7 tmp reads, one float4 weight
#define S2G(U, k0) { \
    float2 t0 = tp[((k0)  )*7], t1 = tp[((k0)+1)*7], \
           t2 = tp[((k0)+2)*7], t3 = tp[((k0)+3)*7]; \
    s.x += U.x * t0.x + U.y * t1.x + U.z * t2.x + U.w * t3.x; \
    s.y += U.x * t0.y + U.y * t1.y + U.z * t2.y + U.w * t3.y; }

// stage-1 h-loop, NG groups of 4 (branch-free body)
#define S1LOOP(NG) \
    for (int hb = 0; hb < span4; hb += 4) { \
        if (act1) { \
            int h = hb + hsub; \
            const float2* cc = fm_s + (ylo + h) * FSTRIDE + offx; \
            float2 a = make_float2(0.f, 0.f); \
            S1G(wx0, 0); \
            if ((NG) > 1) S1G(wx1, 4); \
            if ((NG) > 2) S1G(wx2, 8); \
            tmpw[h * 7 + qx] = a; \
        } \
    }

// stage-2 body for one cell, NG groups of 4 (branch-free)
#define S2BODY(NG, U0, U1, U2) \
    S2G(U0, 0); \
    if ((NG) > 1) S2G(U1, 4); \
    if ((NG) > 2) S2G(U2, 8);

__global__ void __launch_bounds__(512, 2)
roi_main_kernel(const float* __restrict__ fm, float* __restrict__ out) {
    const int cp = blockIdx.x;          // channel pair: c0 = 2*cp
    const int b  = blockIdx.y;
    const int nbase = blockIdx.z * 16;  // 16 n per CTA, one per warp

    __shared__ float2 fm_s[64 * FSTRIDE];       // 34816 B, fully initialized
    __shared__ float2 tmp_s[16][TROWS * 7];     // 60928 B

    const int tid = threadIdx.x;
    const int c0 = cp * 2;

    // ---- stage fm[b][c0..c0+1] interleaved; zero all padding + tmp ----
    {
        const float2 z2 = make_float2(0.f, 0.f);
        // zero rows 56..63 fully, and cols 56..67 of rows 0..55
        for (int i = tid; i < 8 * FSTRIDE; i += 512) fm_s[56 * FSTRIDE + i] = z2;
        for (int i = tid; i < 56 * 12; i += 512) {
            int h = i / 12, w = 56 + (i % 12);
            fm_s[h * FSTRIDE + w] = z2;
        }
        // zero tmp (stage-2 over-reads must stay finite for first roi)
        float2* tz = &tmp_s[0][0];
        for (int i = tid; i < 16 * TROWS * 7; i += 512) tz[i] = z2;

        const float4* s0 = (const float4*)(fm + ((size_t)(b * CC + c0)     ) * (HH * WW));
        const float4* s1 = (const float4*)(fm + ((size_t)(b * CC + c0 + 1)) * (HH * WW));
        for (int i = tid; i < 784; i += 512) {       // 784 float4 per channel
            float4 v0 = s0[i];
            float4 v1 = s1[i];
            int h = i / 14, w = (i % 14) * 4;
            float2* d = &fm_s[h * FSTRIDE + w];
            d[0] = make_float2(v0.x, v1.x);
            d[1] = make_float2(v0.y, v1.y);
            d[2] = make_float2(v0.z, v1.z);
            d[3] = make_float2(v0.w, v1.w);
        }
    }
    __syncthreads();

    const int wid  = tid >> 5;
    const int lane = tid & 31;
    float2* tmpw = tmp_s[wid];

    // stage-1 lane mapping: lanes 0..27 -> (hsub, qx)
    const int qx   = lane % 7;
    const int hsub = lane / 7;
    const bool act1 = (lane < 28);

    // stage-2 cell mapping: cell0 = lane, cell1 = lane+32
    const int p0 = lane / 7,        q0 = lane % 7;
    const int p1 = (lane + 32) / 7, q1 = (lane + 32) % 7;
    const bool has1 = (lane + 32 < 49);

    const int n = nbase + wid;

    float2 acc0 = make_float2(0.f, 0.f);
    float2 acc1 = make_float2(0.f, 0.f);

    #pragma unroll 1
    for (int j = 0; j < 9; j++) {
        const int r = b * R_PER_IMG + ((j == 0) ? n : (NN + n * 8 + (j - 1)));
        const float wroi = (j == 0) ? 1.0f : 0.125f;
        const int yinfo = __ldg(&g_yinfo[r]);
        const int ylo   = yinfo & 0xFF;
        const int span4 = yinfo >> 8;
        const int ky4   = __ldg(&g_kmax[r * 2]);
        const int kx4   = __ldg(&g_kmax[r * 2 + 1]);
        const int mbase = r * 16;
        const float* wbase = g_wgt + (size_t)r * 168;

        // ---- stage 1: x-interp. tmp[h][q] = sum_k wX[q][k]*fm[ylo+h][offx_q+k]
        {
            int metax = __ldg(&g_meta[mbase + 7 + qx]);
            int offx = metax & 0xFF;
            const float4* wx4 = (const float4*)(wbase + (7 + qx) * 12);
            float4 wx0 = __ldg(wx4);
            float4 wx1 = make_float4(0.f, 0.f, 0.f, 0.f);
            float4 wx2 = make_float4(0.f, 0.f, 0.f, 0.f);
            if (kx4 > 4) wx1 = __ldg(wx4 + 1);          // warp-uniform
            if (kx4 > 8) wx2 = __ldg(wx4 + 2);          // warp-uniform
            if (kx4 == 4)      { S1LOOP(1) }
            else if (kx4 == 8) { S1LOOP(2) }
            else               { S1LOOP(3) }
        }
        __syncwarp();

        // ---- stage 2: y-interp. out[p][q] = sum_k wY[p][k]*tmp[offy_p-ylo+k][q]
        {
            int meta0 = __ldg(&g_meta[mbase + p0]);
            int meta1 = has1 ? __ldg(&g_meta[mbase + p1]) : meta0;
            int offy0 = meta0 & 0xFF;
            int offy1 = meta1 & 0xFF;
            const float4* wy40 = (const float4*)(wbase + p0 * 12);
            const float4* wy41 = (const float4*)(wbase + p1 * 12);
            float4 a0 = __ldg(wy40);
            float4 a1 = make_float4(0.f, 0.f, 0.f, 0.f);
            float4 a2 = make_float4(0.f, 0.f, 0.f, 0.f);
            float4 b0 = has1 ? __ldg(wy41) : make_float4(0.f, 0.f, 0.f, 0.f);
            float4 b1 = make_float4(0.f, 0.f, 0.f, 0.f);
            float4 b2 = make_float4(0.f, 0.f, 0.f, 0.f);
            if (ky4 > 4) { a1 = __ldg(wy40 + 1); if (has1) b1 = __ldg(wy41 + 1); }
            if (ky4 > 8) { a2 = __ldg(wy40 + 2); if (has1) b2 = __ldg(wy41 + 2); }

            const float2* tp = tmpw + (offy0 - ylo) * 7 + q0;
            float2 s = make_float2(0.f, 0.f);
            if (ky4 == 4)      { S2BODY(1, a0, a1, a2) }
            else if (ky4 == 8) { S2BODY(2, a0, a1, a2) }
            else               { S2BODY(3, a0, a1, a2) }
            acc0.x += wroi * s.x; acc0.y += wroi * s.y;

            if (has1) {
                tp = tmpw + (offy1 - ylo) * 7 + q1;
                s = make_float2(0.f, 0.f);
                if (ky4 == 4)      { S2BODY(1, b0, b1, b2) }
                else if (ky4 == 8) { S2BODY(2, b0, b1, b2) }
                else               { S2BODY(3, b0, b1, b2) }
                acc1.x += wroi * s.x; acc1.y += wroi * s.y;
            }
        }
        __syncwarp();   // tmp reuse safety before next roi
    }

    // ---- store out[b][n][c][p][q], channels c0 and c0+1 ----
    float* o = out + ((size_t)(b * NN + n) * CC + c0) * (PP * PP);
    o[lane]      = acc0.x;
    o[49 + lane] = acc0.y;
    if (has1) {
        o[lane + 32]      = acc1.x;
        o[49 + lane + 32] = acc1.y;
    }
}

// ---------------------------------------------------------------------------
extern "C" void kernel_launch(void* const* d_in, const int* in_sizes, int n_in,
                              void* d_out, int out_size) {
    const float* fm    = (const float*)d_in[0];
    const float* boxes = (const float*)d_in[1];
    const float* gts   = (const float*)d_in[2];
    float* out = (float*)d_out;

    prep_kernel<<<(R_TOTAL * 2 + 127) / 128, 128>>>(boxes, gts);

    dim3 grid(CC / 2, BB, 4);
    roi_main_kernel<<<grid, 512>>>(fm, out);
}

// round 7
// speedup vs baseline: 1.1140x; 1.0883x over previous
#include <cuda_runtime.h>
#include <cuda_bf16.h>

// Problem constants (fixed by dataset)
#define BB 2
#define CC 256
#define HH 56
#define WW 56
#define NN 64
#define MM 8
#define PP 7
#define R_PER_IMG (NN + NN*MM)        // 576
#define R_TOTAL   (BB * R_PER_IMG)    // 1152
#define MAXK 12

// Per-roi tables.
// g_meta[r*16 + row], row 0..6 = y rows (p), 7..13 = x rows (q). meta = off | (cnt<<8)
// g_yinfo[r] = ylo | (span4<<8)
// g_kmax[r*2 + a] = warp-uniform max cnt for axis a, rounded to mult of 4 (4/8/12)
// g_wgt[(r*14+row)*12 + k], zero-padded to 12 floats per row, 16B aligned
__device__ int   g_meta[R_TOTAL * 16];
__device__ int   g_yinfo[R_TOTAL];
__device__ int   g_kmax[R_TOTAL * 2];
__device__ __align__(16) float g_wgt[R_TOTAL * 14 * MAXK];

// ---------------------------------------------------------------------------
// Kernel A: build sparse interpolation tables for every roi & axis.
// One thread per (roi, axis). Replicates reference math exactly.
// ---------------------------------------------------------------------------
__global__ void prep_kernel(const float* __restrict__ boxes,
                            const float* __restrict__ gts) {
    int t = blockIdx.x * blockDim.x + threadIdx.x;
    if (t >= R_TOTAL * 2) return;
    int r = t >> 1, a = t & 1;
    int b = r / R_PER_IMG, idx = r % R_PER_IMG;

    float x1, y1, x2, y2;
    if (idx < NN) {
        const float* bx = boxes + (b * NN + idx) * 4;
        x1 = bx[0]; y1 = bx[1]; x2 = bx[2]; y2 = bx[3];
    } else {
        int n = (idx - NN) >> 3, m = (idx - NN) & 7;
        const float* bx = boxes + (b * NN + n) * 4;
        const float* gx = gts   + (b * MM + m) * 4;
        x1 = fminf(bx[0], gx[0]); y1 = fminf(bx[1], gx[1]);
        x2 = fmaxf(bx[2], gx[2]); y2 = fmaxf(bx[3], gx[3]);
    }

    float start = a ? x1 : y1;
    float len   = fmaxf(a ? (x2 - x1) : (y2 - y1), 1.0f);
    const float dimf = 56.0f;
    const int   dim  = 56;

    float bin = len / 7.0f;
    int   g   = (int)ceilf(bin);           // grid = ceil(length/P)
    float gf  = (float)g;
    float inv = 1.0f / gf;

    int lo_min = 1 << 20, hi_max = -1, cnt_max = 1;
    for (int p = 0; p < 7; p++) {
        float acc[MAXK];
        #pragma unroll
        for (int k = 0; k < MAXK; k++) acc[k] = 0.0f;
        int base = -1, hi = -1;
        float c0 = start + (float)p * bin;
        for (int s = 0; s < 8; s++) {
            if (s >= g) break;
            float coord = c0 + ((float)s + 0.5f) * bin / gf;
            if (!(coord >= -1.0f && coord <= dimf)) continue;
            float c = fmaxf(coord, 0.0f);
            int low = (int)floorf(c);
            int high; float cv;
            if (low >= dim - 1) { low = dim - 1; high = dim - 1; cv = (float)low; }
            else                { high = low + 1; cv = c; }
            float l  = cv - (float)low;
            float wl = (1.0f - l) * inv;
            float wh = l * inv;
            if (base < 0) base = low;
            int d  = low  - base;
            int d2 = high - base;
            if (d  >= 0 && d  < MAXK) acc[d]  += wl;
            if (d2 >= 0 && d2 < MAXK) acc[d2] += wh;
            if (high > hi) hi = high;
        }
        int cnt = (base < 0) ? 0 : (hi - base + 1);
        if (base < 0) base = 0;
        if (cnt > MAXK) cnt = MAXK;   // safety (true bound is 10)
        if (base < lo_min) lo_min = base;
        if (base + cnt > hi_max) hi_max = base + cnt;
        if (cnt > cnt_max) cnt_max = cnt;
        g_meta[r * 16 + a * 7 + p] = base | (cnt << 8);
        float* wp = g_wgt + (size_t)((r * 14 + a * 7 + p)) * MAXK;
        #pragma unroll
        for (int k = 0; k < MAXK; k++) wp[k] = acc[k];
    }
    int km = (cnt_max + 3) & ~3;          // 4, 8 or 12
    if (km < 4)  km = 4;
    if (km > 12) km = 12;
    g_kmax[r * 2 + a] = km;
    if (a == 0) {
        int lo = lo_min, span = hi_max - lo_min;
        if (span < 1) { lo = 0; span = 1; }
        int span4 = (span + 3) & ~3;
        g_yinfo[r] = lo | (span4 << 8);
    }
}

// ---------------------------------------------------------------------------
// Kernel B: main compute. One CTA per (channel-pair, image, n-eighth).
// fm for 2 channels interleaved in smem (68-col row stride). Column 60 of
// every accessible row is ZERO; finished taps (k >= cnt) are redirected to it
// by a branch-free address SELECT, so their crossbar cost collapses to a
// broadcast of <=4 shared zero words per instruction. tmp row 63 is the
// analogous zero row for stage 2. Weights are zero-padded, so the dummy
// values contribute exactly 0.
// 8 warps, one n each; per n: box roi + 8 ctx rois.
// ---------------------------------------------------------------------------
#define FSTRIDE 68
#define TROWS   64
#define ZCOL    60
#define ZROW    63

// stage-1 tap: unconditional LDS.64 at per-roi precomputed byte offset cx[K]
#define S1TAP(W, K) { \
    float2 f = *(const float2*)(rowb + cx[(K)]); \
    a.x += (W) * f.x; a.y += (W) * f.y; }

// stage-2 tap: branch-free address select into tmp (row ZROW = zeros)
#define S2TAP(W, K, basei, cnti, zbi) { \
    int ai = (basei) + (K) * 7; \
    if ((K) >= (cnti)) ai = (zbi); \
    float2 tv = *(const float2*)(tb + ai * 8); \
    s.x += (W) * tv.x; s.y += (W) * tv.y; }

// stage-1 h-loop, NG groups of 4 taps (branch-free body)
#define S1LOOP(NG) \
    for (int hb = 0; hb < span4; hb += 4) { \
        if (act1) { \
            int h = hb + hsub; \
            const char* rowb = (const char*)fm_s + (ylo + h) * (FSTRIDE * 8); \
            float2 a = make_float2(0.f, 0.f); \
            S1TAP(wx0.x, 0) S1TAP(wx0.y, 1) S1TAP(wx0.z, 2) S1TAP(wx0.w, 3) \
            if ((NG) > 1) { S1TAP(wx1.x, 4) S1TAP(wx1.y, 5) S1TAP(wx1.z, 6) S1TAP(wx1.w, 7) } \
            if ((NG) > 2) { S1TAP(wx2.x, 8) S1TAP(wx2.y, 9) S1TAP(wx2.z, 10) S1TAP(wx2.w, 11) } \
            tmpw[h * 7 + qx] = a; \
        } \
    }

// stage-2 body for one cell, NG groups of 4 taps (branch-free)
#define S2BODY(NG, U0, U1, U2, basei, cnti, zbi) \
    S2TAP(U0.x, 0, basei, cnti, zbi) S2TAP(U0.y, 1, basei, cnti, zbi) \
    S2TAP(U0.z, 2, basei, cnti, zbi) S2TAP(U0.w, 3, basei, cnti, zbi) \
    if ((NG) > 1) { S2TAP(U1.x, 4, basei, cnti, zbi) S2TAP(U1.y, 5, basei, cnti, zbi) \
                    S2TAP(U1.z, 6, basei, cnti, zbi) S2TAP(U1.w, 7, basei, cnti, zbi) } \
    if ((NG) > 2) { S2TAP(U2.x, 8, basei, cnti, zbi) S2TAP(U2.y, 9, basei, cnti, zbi) \
                    S2TAP(U2.z, 10, basei, cnti, zbi) S2TAP(U2.w, 11, basei, cnti, zbi) }

__global__ void __launch_bounds__(256, 3)
roi_main_kernel(const float* __restrict__ fm, float* __restrict__ out) {
    const int cp = blockIdx.x;          // channel pair: c0 = 2*cp
    const int b  = blockIdx.y;
    const int nbase = blockIdx.z * 8;   // 8 n per CTA, one per warp

    __shared__ float2 fm_s[60 * FSTRIDE];       // 32640 B (rows 0..59)
    __shared__ float2 tmp_s[8][TROWS * 7];      // 28672 B

    const int tid = threadIdx.x;
    const int c0 = cp * 2;

    // ---- stage fm[b][c0..c0+1] interleaved; zero pads ----
    {
        const float2 z2 = make_float2(0.f, 0.f);
        // rows 56..59 fully zero (h over-read rows; includes their ZCOL)
        for (int i = tid; i < 4 * FSTRIDE; i += 256) fm_s[56 * FSTRIDE + i] = z2;
        // ZCOL zero in rows 0..55
        if (tid < 56) fm_s[tid * FSTRIDE + ZCOL] = z2;
        // tmp zero row (ZROW) for each warp
        if (tid < 56) tmp_s[tid / 7][ZROW * 7 + (tid % 7)] = z2;

        const float4* s0 = (const float4*)(fm + ((size_t)(b * CC + c0)     ) * (HH * WW));
        const float4* s1 = (const float4*)(fm + ((size_t)(b * CC + c0 + 1)) * (HH * WW));
        for (int i = tid; i < 784; i += 256) {       // 784 float4 per channel
            float4 v0 = s0[i];
            float4 v1 = s1[i];
            int h = i / 14, w = (i % 14) * 4;
            float2* d = &fm_s[h * FSTRIDE + w];
            d[0] = make_float2(v0.x, v1.x);
            d[1] = make_float2(v0.y, v1.y);
            d[2] = make_float2(v0.z, v1.z);
            d[3] = make_float2(v0.w, v1.w);
        }
    }
    __syncthreads();

    const int wid  = tid >> 5;
    const int lane = tid & 31;
    float2* tmpw = tmp_s[wid];
    const char* tb = (const char*)tmpw;

    // stage-1 lane mapping: lanes 0..27 -> (hsub, qx)
    const int qx   = lane % 7;
    const int hsub = lane / 7;
    const bool act1 = (lane < 28);

    // stage-2 cell mapping: cell0 = lane, cell1 = lane+32
    const int p0 = lane / 7,        q0 = lane % 7;
    const int p1 = (lane + 32) / 7, q1 = (lane + 32) % 7;
    const bool has1 = (lane + 32 < 49);
    const int zb0 = ZROW * 7 + q0;
    const int zb1 = ZROW * 7 + q1;

    const int n = nbase + wid;

    float2 acc0 = make_float2(0.f, 0.f);
    float2 acc1 = make_float2(0.f, 0.f);

    #pragma unroll 1
    for (int j = 0; j < 9; j++) {
        const int r = b * R_PER_IMG + ((j == 0) ? n : (NN + n * 8 + (j - 1)));
        const float wroi = (j == 0) ? 1.0f : 0.125f;
        const int yinfo = __ldg(&g_yinfo[r]);
        const int ylo   = yinfo & 0xFF;
        const int span4 = yinfo >> 8;
        const int ky4   = __ldg(&g_kmax[r * 2]);
        const int kx4   = __ldg(&g_kmax[r * 2 + 1]);
        const int mbase = r * 16;
        const float* wbase = g_wgt + (size_t)r * 168;

        // ---- stage 1: x-interp. tmp[h][q] = sum_k wX[q][k]*fm[ylo+h][offx_q+k]
        {
            int metax = __ldg(&g_meta[mbase + 7 + qx]);
            int offx = metax & 0xFF, cntx = metax >> 8;
            // per-roi byte-offset table; finished taps redirected to ZCOL
            int cx[12];
            #pragma unroll
            for (int k = 0; k < 12; k++)
                cx[k] = ((k < cntx) ? (offx + k) : ZCOL) * 8;
            const float4* wx4 = (const float4*)(wbase + (7 + qx) * 12);
            float4 wx0 = __ldg(wx4);
            float4 wx1 = make_float4(0.f, 0.f, 0.f, 0.f);
            float4 wx2 = make_float4(0.f, 0.f, 0.f, 0.f);
            if (kx4 > 4) wx1 = __ldg(wx4 + 1);          // warp-uniform
            if (kx4 > 8) wx2 = __ldg(wx4 + 2);          // warp-uniform
            if (kx4 == 4)      { S1LOOP(1) }
            else if (kx4 == 8) { S1LOOP(2) }
            else               { S1LOOP(3) }
        }
        __syncwarp();

        // ---- stage 2: y-interp. out[p][q] = sum_k wY[p][k]*tmp[offy_p-ylo+k][q]
        {
            int meta0 = __ldg(&g_meta[mbase + p0]);
            int meta1 = has1 ? __ldg(&g_meta[mbase + p1]) : meta0;
            int offy0 = meta0 & 0xFF, cnt0 = meta0 >> 8;
            int offy1 = meta1 & 0xFF, cnt1 = meta1 >> 8;
            int base0 = (offy0 - ylo) * 7 + q0;
            int base1 = (offy1 - ylo) * 7 + q1;
            const float4* wy40 = (const float4*)(wbase + p0 * 12);
            const float4* wy41 = (const float4*)(wbase + p1 * 12);
            float4 a0 = __ldg(wy40);
            float4 a1 = make_float4(0.f, 0.f, 0.f, 0.f);
            float4 a2 = make_float4(0.f, 0.f, 0.f, 0.f);
            float4 b0 = has1 ? __ldg(wy41) : make_float4(0.f, 0.f, 0.f, 0.f);
            float4 b1 = make_float4(0.f, 0.f, 0.f, 0.f);
            float4 b2 = make_float4(0.f, 0.f, 0.f, 0.f);
            if (ky4 > 4) { a1 = __ldg(wy40 + 1); if (has1) b1 = __ldg(wy41 + 1); }
            if (ky4 > 8) { a2 = __ldg(wy40 + 2); if (has1) b2 = __ldg(wy41 + 2); }

            float2 s = make_float2(0.f, 0.f);
            if (ky4 == 4)      { S2BODY(1, a0, a1, a2, base0, cnt0, zb0) }
            else if (ky4 == 8) { S2BODY(2, a0, a1, a2, base0, cnt0, zb0) }
            else               { S2BODY(3, a0, a1, a2, base0, cnt0, zb0) }
            acc0.x += wroi * s.x; acc0.y += wroi * s.y;

            if (has1) {
                s = make_float2(0.f, 0.f);
                if (ky4 == 4)      { S2BODY(1, b0, b1, b2, base1, cnt1, zb1) }
                else if (ky4 == 8) { S2BODY(2, b0, b1, b2, base1, cnt1, zb1) }
                else               { S2BODY(3, b0, b1, b2, base1, cnt1, zb1) }
                acc1.x += wroi * s.x; acc1.y += wroi * s.y;
            }
        }
        __syncwarp();   // tmp reuse safety before next roi
    }

    // ---- store out[b][n][c][p][q], channels c0 and c0+1 ----
    float* o = out + ((size_t)(b * NN + n) * CC + c0) * (PP * PP);
    o[lane]      = acc0.x;
    o[49 + lane] = acc0.y;
    if (has1) {
        o[lane + 32]      = acc1.x;
        o[49 + lane + 32] = acc1.y;
    }
}

// ---------------------------------------------------------------------------
extern "C" void kernel_launch(void* const* d_in, const int* in_sizes, int n_in,
                              void* d_out, int out_size) {
    const float* fm    = (const float*)d_in[0];
    const float* boxes = (const float*)d_in[1];
    const float* gts   = (const float*)d_in[2];
    float* out = (float*)d_out;

    prep_kernel<<<(R_TOTAL * 2 + 127) / 128, 128>>>(boxes, gts);

    dim3 grid(CC / 2, BB, 8);
    roi_main_kernel<<<grid, 256>>>(fm, out);
}

// round 8
// speedup vs baseline: 1.1526x; 1.0346x over previous
#include <cuda_runtime.h>
#include <cuda_bf16.h>

// Problem constants (fixed by dataset)
#define BB 2
#define CC 256
#define HH 56
#define WW 56
#define NN 64
#define MM 8
#define PP 7
#define R_PER_IMG (NN + NN*MM)        // 576
#define R_TOTAL   (BB * R_PER_IMG)    // 1152
#define MAXK 12

// Per-roi tables.
// g_meta[r*16 + row], row 0..6 = y rows (p), 7..13 = x rows (q). meta = off | (cnt<<8)
// g_yinfo[r] = ylo | (span4<<8)
// g_kmax[r*2 + a] = warp-uniform max cnt for axis a, rounded UP to mult of 2 (2..12)
// g_wgt[(r*14+row)*12 + k], zero-padded to 12 floats per row, 16B aligned
__device__ int   g_meta[R_TOTAL * 16];
__device__ int   g_yinfo[R_TOTAL];
__device__ int   g_kmax[R_TOTAL * 2];
__device__ __align__(16) float g_wgt[R_TOTAL * 14 * MAXK];

// ---------------------------------------------------------------------------
// Kernel A: build sparse interpolation tables for every roi & axis.
// One thread per (roi, axis). Replicates reference math exactly.
// ---------------------------------------------------------------------------
__global__ void prep_kernel(const float* __restrict__ boxes,
                            const float* __restrict__ gts) {
    int t = blockIdx.x * blockDim.x + threadIdx.x;
    if (t >= R_TOTAL * 2) return;
    int r = t >> 1, a = t & 1;
    int b = r / R_PER_IMG, idx = r % R_PER_IMG;

    float x1, y1, x2, y2;
    if (idx < NN) {
        const float* bx = boxes + (b * NN + idx) * 4;
        x1 = bx[0]; y1 = bx[1]; x2 = bx[2]; y2 = bx[3];
    } else {
        int n = (idx - NN) >> 3, m = (idx - NN) & 7;
        const float* bx = boxes + (b * NN + n) * 4;
        const float* gx = gts   + (b * MM + m) * 4;
        x1 = fminf(bx[0], gx[0]); y1 = fminf(bx[1], gx[1]);
        x2 = fmaxf(bx[2], gx[2]); y2 = fmaxf(bx[3], gx[3]);
    }

    float start = a ? x1 : y1;
    float len   = fmaxf(a ? (x2 - x1) : (y2 - y1), 1.0f);
    const float dimf = 56.0f;
    const int   dim  = 56;

    float bin = len / 7.0f;
    int   g   = (int)ceilf(bin);           // grid = ceil(length/P)
    float gf  = (float)g;
    float inv = 1.0f / gf;

    int lo_min = 1 << 20, hi_max = -1, cnt_max = 1;
    for (int p = 0; p < 7; p++) {
        float acc[MAXK];
        #pragma unroll
        for (int k = 0; k < MAXK; k++) acc[k] = 0.0f;
        int base = -1, hi = -1;
        float c0 = start + (float)p * bin;
        for (int s = 0; s < 8; s++) {
            if (s >= g) break;
            float coord = c0 + ((float)s + 0.5f) * bin / gf;
            if (!(coord >= -1.0f && coord <= dimf)) continue;
            float c = fmaxf(coord, 0.0f);
            int low = (int)floorf(c);
            int high; float cv;
            if (low >= dim - 1) { low = dim - 1; high = dim - 1; cv = (float)low; }
            else                { high = low + 1; cv = c; }
            float l  = cv - (float)low;
            float wl = (1.0f - l) * inv;
            float wh = l * inv;
            if (base < 0) base = low;
            int d  = low  - base;
            int d2 = high - base;
            if (d  >= 0 && d  < MAXK) acc[d]  += wl;
            if (d2 >= 0 && d2 < MAXK) acc[d2] += wh;
            if (high > hi) hi = high;
        }
        int cnt = (base < 0) ? 0 : (hi - base + 1);
        if (base < 0) base = 0;
        if (cnt > MAXK) cnt = MAXK;   // safety (true bound is 10)
        if (base < lo_min) lo_min = base;
        if (base + cnt > hi_max) hi_max = base + cnt;
        if (cnt > cnt_max) cnt_max = cnt;
        g_meta[r * 16 + a * 7 + p] = base | (cnt << 8);
        float* wp = g_wgt + (size_t)((r * 14 + a * 7 + p)) * MAXK;
        #pragma unroll
        for (int k = 0; k < MAXK; k++) wp[k] = acc[k];
    }
    int km = (cnt_max + 1) & ~1;          // 2,4,6,8,10,12
    if (km < 2)  km = 2;
    if (km > 12) km = 12;
    g_kmax[r * 2 + a] = km;
    if (a == 0) {
        int lo = lo_min, span = hi_max - lo_min;
        if (span < 1) { lo = 0; span = 1; }
        int span4 = (span + 3) & ~3;
        g_yinfo[r] = lo | (span4 << 8);
    }
}

// ---------------------------------------------------------------------------
// Kernel B: main compute. One CTA per (channel-pair, image, n-eighth).
// fm for 2 channels interleaved in smem (68-col row stride). Column 60 of
// every accessible row is ZERO; taps with k >= cnt are redirected to it by a
// branch-free inline address SELECT. tmp row 63 is the analogous zero row for
// stage 2. Weights are zero-padded, so dummy taps contribute exactly 0.
// Inner bodies are selected ONCE per roi from 6 branch-free variants via the
// warp-uniform per-roi kmax rounded to 2 -> near-minimal tap instructions
// with full load batching.
// ---------------------------------------------------------------------------
#define FSTRIDE 68
#define TROWS   64
#define ZCOL    60
#define ZROW    63

// ---- stage-1 tap: inline zero-redirect select + LDS.64 ----
#define S1TAP(W, K) { \
    int ai = off8 + (K) * 8; \
    if ((K) >= cntx) ai = (ZCOL * 8); \
    float2 f = *(const float2*)(rowb + ai); \
    a.x += (W) * f.x; a.y += (W) * f.y; }

#define T1_2  S1TAP(wx0.x, 0) S1TAP(wx0.y, 1)
#define T1_4  T1_2  S1TAP(wx0.z, 2)  S1TAP(wx0.w, 3)
#define T1_6  T1_4  S1TAP(wx1.x, 4)  S1TAP(wx1.y, 5)
#define T1_8  T1_6  S1TAP(wx1.z, 6)  S1TAP(wx1.w, 7)
#define T1_10 T1_8  S1TAP(wx2.x, 8)  S1TAP(wx2.y, 9)
#define T1_12 T1_10 S1TAP(wx2.z, 10) S1TAP(wx2.w, 11)

#define S1LOOP(TAPS) \
    for (int hb = 0; hb < span4; hb += 4) { \
        if (act1) { \
            int h = hb + hsub; \
            const char* rowb = (const char*)fm_s + (ylo + h) * (FSTRIDE * 8); \
            float2 a = make_float2(0.f, 0.f); \
            TAPS \
            tmpw[h * 7 + qx] = a; \
        } \
    }

// ---- stage-2 tap: inline zero-redirect select + LDS.64 from tmp ----
#define S2TAP(W, K) { \
    int ai = base_c + (K) * 7; \
    if ((K) >= cnt_c) ai = zb_c; \
    float2 tv = *(const float2*)(tb + ai * 8); \
    s.x += (W) * tv.x; s.y += (W) * tv.y; }

#define T2_2  S2TAP(u0.x, 0) S2TAP(u0.y, 1)
#define T2_4  T2_2  S2TAP(u0.z, 2)  S2TAP(u0.w, 3)
#define T2_6  T2_4  S2TAP(u1.x, 4)  S2TAP(u1.y, 5)
#define T2_8  T2_6  S2TAP(u1.z, 6)  S2TAP(u1.w, 7)
#define T2_10 T2_8  S2TAP(u2.x, 8)  S2TAP(u2.y, 9)
#define T2_12 T2_10 S2TAP(u2.z, 10) S2TAP(u2.w, 11)

#define S2SWITCH \
    switch (ky2) { \
        case 2:  { T2_2  } break; \
        case 4:  { T2_4  } break; \
        case 6:  { T2_6  } break; \
        case 8:  { T2_8  } break; \
        case 10: { T2_10 } break; \
        default: { T2_12 } break; \
    }

__global__ void __launch_bounds__(256, 3)
roi_main_kernel(const float* __restrict__ fm, float* __restrict__ out) {
    const int cp = blockIdx.x;          // channel pair: c0 = 2*cp
    const int b  = blockIdx.y;
    const int nbase = blockIdx.z * 8;   // 8 n per CTA, one per warp

    __shared__ float2 fm_s[60 * FSTRIDE];       // 32640 B (rows 0..59)
    __shared__ float2 tmp_s[8][TROWS * 7];      // 28672 B

    const int tid = threadIdx.x;
    const int c0 = cp * 2;

    // ---- stage fm[b][c0..c0+1] interleaved; zero pads ----
    {
        const float2 z2 = make_float2(0.f, 0.f);
        // rows 56..59 fully zero (h over-read rows; includes their ZCOL)
        for (int i = tid; i < 4 * FSTRIDE; i += 256) fm_s[56 * FSTRIDE + i] = z2;
        // ZCOL zero in rows 0..55
        if (tid < 56) fm_s[tid * FSTRIDE + ZCOL] = z2;
        // tmp zero row (ZROW) for each warp
        if (tid < 56) tmp_s[tid / 7][ZROW * 7 + (tid % 7)] = z2;

        const float4* s0 = (const float4*)(fm + ((size_t)(b * CC + c0)     ) * (HH * WW));
        const float4* s1 = (const float4*)(fm + ((size_t)(b * CC + c0 + 1)) * (HH * WW));
        for (int i = tid; i < 784; i += 256) {       // 784 float4 per channel
            float4 v0 = s0[i];
            float4 v1 = s1[i];
            int h = i / 14, w = (i % 14) * 4;
            float2* d = &fm_s[h * FSTRIDE + w];
            d[0] = make_float2(v0.x, v1.x);
            d[1] = make_float2(v0.y, v1.y);
            d[2] = make_float2(v0.z, v1.z);
            d[3] = make_float2(v0.w, v1.w);
        }
    }
    __syncthreads();

    const int wid  = tid >> 5;
    const int lane = tid & 31;
    float2* tmpw = tmp_s[wid];
    const char* tb = (const char*)tmpw;

    // stage-1 lane mapping: lanes 0..27 -> (hsub, qx)
    const int qx   = lane % 7;
    const int hsub = lane / 7;
    const bool act1 = (lane < 28);

    // stage-2 cell mapping: cell0 = lane, cell1 = lane+32
    const int p0 = lane / 7,        q0 = lane % 7;
    const int p1 = (lane + 32) / 7, q1 = (lane + 32) % 7;
    const bool has1 = (lane + 32 < 49);
    const int zb0 = ZROW * 7 + q0;
    const int zb1 = ZROW * 7 + q1;

    const int n = nbase + wid;

    float2 acc0 = make_float2(0.f, 0.f);
    float2 acc1 = make_float2(0.f, 0.f);

    #pragma unroll 1
    for (int j = 0; j < 9; j++) {
        const int r = b * R_PER_IMG + ((j == 0) ? n : (NN + n * 8 + (j - 1)));
        const float wroi = (j == 0) ? 1.0f : 0.125f;
        const int yinfo = __ldg(&g_yinfo[r]);
        const int ylo   = yinfo & 0xFF;
        const int span4 = yinfo >> 8;
        const int ky2   = __ldg(&g_kmax[r * 2]);
        const int kx2   = __ldg(&g_kmax[r * 2 + 1]);
        const int mbase = r * 16;
        const float* wbase = g_wgt + (size_t)r * 168;

        // ---- stage 1: x-interp. tmp[h][q] = sum_k wX[q][k]*fm[ylo+h][offx_q+k]
        {
            int metax = __ldg(&g_meta[mbase + 7 + qx]);
            int offx = metax & 0xFF, cntx = metax >> 8;
            int off8 = offx * 8;
            const float4* wx4 = (const float4*)(wbase + (7 + qx) * 12);
            float4 wx0 = __ldg(wx4);
            float4 wx1 = make_float4(0.f, 0.f, 0.f, 0.f);
            float4 wx2 = make_float4(0.f, 0.f, 0.f, 0.f);
            if (kx2 > 4) wx1 = __ldg(wx4 + 1);          // warp-uniform
            if (kx2 > 8) wx2 = __ldg(wx4 + 2);          // warp-uniform
            switch (kx2) {
                case 2:  { S1LOOP(T1_2)  } break;
                case 4:  { S1LOOP(T1_4)  } break;
                case 6:  { S1LOOP(T1_6)  } break;
                case 8:  { S1LOOP(T1_8)  } break;
                case 10: { S1LOOP(T1_10) } break;
                default: { S1LOOP(T1_12) } break;
            }
        }
        __syncwarp();

        // ---- stage 2: y-interp. out[p][q] = sum_k wY[p][k]*tmp[offy_p-ylo+k][q]
        {
            int meta0 = __ldg(&g_meta[mbase + p0]);
            int meta1 = has1 ? __ldg(&g_meta[mbase + p1]) : meta0;
            const float4* wy40 = (const float4*)(wbase + p0 * 12);
            const float4* wy41 = (const float4*)(wbase + p1 * 12);
            float4 a0 = __ldg(wy40);
            float4 a1 = make_float4(0.f, 0.f, 0.f, 0.f);
            float4 a2 = make_float4(0.f, 0.f, 0.f, 0.f);
            float4 b0 = has1 ? __ldg(wy41) : make_float4(0.f, 0.f, 0.f, 0.f);
            float4 b1 = make_float4(0.f, 0.f, 0.f, 0.f);
            float4 b2 = make_float4(0.f, 0.f, 0.f, 0.f);
            if (ky2 > 4) { a1 = __ldg(wy40 + 1); if (has1) b1 = __ldg(wy41 + 1); }
            if (ky2 > 8) { a2 = __ldg(wy40 + 2); if (has1) b2 = __ldg(wy41 + 2); }

            {
                int base_c = ((meta0 & 0xFF) - ylo) * 7 + q0;
                int cnt_c  = meta0 >> 8;
                int zb_c   = zb0;
                float4 u0 = a0, u1 = a1, u2 = a2;
                float2 s = make_float2(0.f, 0.f);
                S2SWITCH
                acc0.x += wroi * s.x; acc0.y += wroi * s.y;
            }
            if (has1) {
                int base_c = ((meta1 & 0xFF) - ylo) * 7 + q1;
                int cnt_c  = meta1 >> 8;
                int zb_c   = zb1;
                float4 u0 = b0, u1 = b1, u2 = b2;
                float2 s = make_float2(0.f, 0.f);
                S2SWITCH
                acc1.x += wroi * s.x; acc1.y += wroi * s.y;
            }
        }
        __syncwarp();   // tmp reuse safety before next roi
    }

    // ---- store out[b][n][c][p][q], channels c0 and c0+1 ----
    float* o = out + ((size_t)(b * NN + n) * CC + c0) * (PP * PP);
    o[lane]      = acc0.x;
    o[49 + lane] = acc0.y;
    if (has1) {
        o[lane + 32]      = acc1.x;
        o[49 + lane + 32] = acc1.y;
    }
}

// ---------------------------------------------------------------------------
extern "C" void kernel_launch(void* const* d_in, const int* in_sizes, int n_in,
                              void* d_out, int out_size) {
    const float* fm    = (const float*)d_in[0];
    const float* boxes = (const float*)d_in[1];
    const float* gts   = (const float*)d_in[2];
    float* out = (float*)d_out;

    prep_kernel<<<(R_TOTAL * 2 + 127) / 128, 128>>>(boxes, gts);

    dim3 grid(CC / 2, BB, 8);
    roi_main_kernel<<<grid, 256>>>(fm, out);
}

// round 9
// speedup vs baseline: 1.1734x; 1.0181x over previous
#include <cuda_runtime.h>
#include <cuda_bf16.h>

// Problem constants (fixed by dataset)
#define BB 2
#define CC 256
#define HH 56
#define WW 56
#define NN 64
#define MM 8
#define PP 7
#define R_PER_IMG (NN + NN*MM)        // 576
#define R_TOTAL   (BB * R_PER_IMG)    // 1152
#define MAXK 12

#define FSTRIDE 68
#define TROWS   64
#define ZCOL    60
#define ZROW    63

// Per-roi tables.
// g_meta[r*16 + row], row 0..6 = y rows (p), 7..13 = x rows (q). meta = off | (cnt<<8)
// g_yinfo[r] = ylo | (span4<<8)
// g_kmax[r*2 + a] = warp-uniform EXACT max cnt for axis a (1..12)
// g_wgt[(r*14+row)*12 + k], zero-padded to 12 floats per row, 16B aligned
__device__ int   g_meta[R_TOTAL * 16];
__device__ int   g_yinfo[R_TOTAL];
__device__ int   g_kmax[R_TOTAL * 2];
__device__ __align__(16) float g_wgt[R_TOTAL * 14 * MAXK];

// ---------------------------------------------------------------------------
// Kernel A: build sparse interpolation tables for every roi & axis.
// One thread per (roi, axis). Replicates reference math exactly.
// ---------------------------------------------------------------------------
__global__ void prep_kernel(const float* __restrict__ boxes,
                            const float* __restrict__ gts) {
    int t = blockIdx.x * blockDim.x + threadIdx.x;
    if (t >= R_TOTAL * 2) return;
    int r = t >> 1, a = t & 1;
    int b = r / R_PER_IMG, idx = r % R_PER_IMG;

    float x1, y1, x2, y2;
    if (idx < NN) {
        const float* bx = boxes + (b * NN + idx) * 4;
        x1 = bx[0]; y1 = bx[1]; x2 = bx[2]; y2 = bx[3];
    } else {
        int n = (idx - NN) >> 3, m = (idx - NN) & 7;
        const float* bx = boxes + (b * NN + n) * 4;
        const float* gx = gts   + (b * MM + m) * 4;
        x1 = fminf(bx[0], gx[0]); y1 = fminf(bx[1], gx[1]);
        x2 = fmaxf(bx[2], gx[2]); y2 = fmaxf(bx[3], gx[3]);
    }

    float start = a ? x1 : y1;
    float len   = fmaxf(a ? (x2 - x1) : (y2 - y1), 1.0f);
    const float dimf = 56.0f;
    const int   dim  = 56;

    float bin = len / 7.0f;
    int   g   = (int)ceilf(bin);           // grid = ceil(length/P)
    float gf  = (float)g;
    float inv = 1.0f / gf;

    int lo_min = 1 << 20, hi_max = -1, cnt_max = 1;
    for (int p = 0; p < 7; p++) {
        float acc[MAXK];
        #pragma unroll
        for (int k = 0; k < MAXK; k++) acc[k] = 0.0f;
        int base = -1, hi = -1;
        float c0 = start + (float)p * bin;
        for (int s = 0; s < 8; s++) {
            if (s >= g) break;
            float coord = c0 + ((float)s + 0.5f) * bin / gf;
            if (!(coord >= -1.0f && coord <= dimf)) continue;
            float c = fmaxf(coord, 0.0f);
            int low = (int)floorf(c);
            int high; float cv;
            if (low >= dim - 1) { low = dim - 1; high = dim - 1; cv = (float)low; }
            else                { high = low + 1; cv = c; }
            float l  = cv - (float)low;
            float wl = (1.0f - l) * inv;
            float wh = l * inv;
            if (base < 0) base = low;
            int d  = low  - base;
            int d2 = high - base;
            if (d  >= 0 && d  < MAXK) acc[d]  += wl;
            if (d2 >= 0 && d2 < MAXK) acc[d2] += wh;
            if (high > hi) hi = high;
        }
        int cnt = (base < 0) ? 0 : (hi - base + 1);
        if (base < 0) base = 0;
        if (cnt > MAXK) cnt = MAXK;   // safety (true bound is 10)
        if (base < lo_min) lo_min = base;
        if (base + cnt > hi_max) hi_max = base + cnt;
        if (cnt > cnt_max) cnt_max = cnt;
        g_meta[r * 16 + a * 7 + p] = base | (cnt << 8);
        float* wp = g_wgt + (size_t)((r * 14 + a * 7 + p)) * MAXK;
        #pragma unroll
        for (int k = 0; k < MAXK; k++) wp[k] = acc[k];
    }
    if (cnt_max < 1)  cnt_max = 1;
    if (cnt_max > 12) cnt_max = 12;
    g_kmax[r * 2 + a] = cnt_max;           // exact, granularity 1
    if (a == 0) {
        int lo = lo_min, span = hi_max - lo_min;
        if (span < 1) { lo = 0; span = 1; }
        int span4 = (span + 3) & ~3;
        g_yinfo[r] = lo | (span4 << 8);
    }
}

// ---------------------------------------------------------------------------
// Stage bodies: templated on exact warp-uniform tap count KM, fully unrolled,
// branch-free; per-lane taps with k >= cnt are redirected to a shared zero
// word (ZCOL column / ZROW row) by an inline address select, so per-lane cnt
// is exact at zero extra wavefront cost. Weights are zero-padded.
// ---------------------------------------------------------------------------
template<int KM>
__device__ __forceinline__ void s1loop(const char* fmb, float2* tmpw,
        int ylo, int span4, int hsub, int qx, bool act1,
        int off8, int cntx, const float* w) {
    #pragma unroll 1
    for (int hb = 0; hb < span4; hb += 4) {
        if (act1) {
            int h = hb + hsub;
            const char* rowb = fmb + (ylo + h) * (FSTRIDE * 8);
            float2 a = make_float2(0.f, 0.f);
            #pragma unroll
            for (int k = 0; k < KM; k++) {
                int ai = off8 + k * 8;
                if (k >= cntx) ai = ZCOL * 8;
                float2 f = *(const float2*)(rowb + ai);
                a.x += w[k] * f.x; a.y += w[k] * f.y;
            }
            tmpw[h * 7 + qx] = a;
        }
    }
}

template<int KM>
__device__ __forceinline__ float2 s2cell(const char* tb, int base, int cnt,
                                         int zb, const float* u) {
    float2 s = make_float2(0.f, 0.f);
    #pragma unroll
    for (int k = 0; k < KM; k++) {
        int ai = base + k * 7;
        if (k >= cnt) ai = zb;
        float2 tv = *(const float2*)(tb + ai * 8);
        s.x += u[k] * tv.x; s.y += u[k] * tv.y;
    }
    return s;
}

// ---------------------------------------------------------------------------
// Kernel B: main compute. One CTA per (channel-pair, image, n-eighth).
// fm for 2 channels interleaved in smem (68-col row stride); ZCOL zeroed.
// 8 warps, one n each; per n: box roi + 8 ctx rois, 7x7 out in registers.
// ---------------------------------------------------------------------------
__global__ void __launch_bounds__(256, 3)
roi_main_kernel(const float* __restrict__ fm, float* __restrict__ out) {
    const int cp = blockIdx.x;          // channel pair: c0 = 2*cp
    const int b  = blockIdx.y;
    const int nbase = blockIdx.z * 8;   // 8 n per CTA, one per warp

    __shared__ float2 fm_s[60 * FSTRIDE];       // 32640 B (rows 0..59)
    __shared__ float2 tmp_s[8][TROWS * 7];      // 28672 B

    const int tid = threadIdx.x;
    const int c0 = cp * 2;

    // ---- stage fm[b][c0..c0+1] interleaved; zero pads ----
    {
        const float2 z2 = make_float2(0.f, 0.f);
        for (int i = tid; i < 4 * FSTRIDE; i += 256) fm_s[56 * FSTRIDE + i] = z2;
        if (tid < 56) fm_s[tid * FSTRIDE + ZCOL] = z2;
        if (tid < 56) tmp_s[tid / 7][ZROW * 7 + (tid % 7)] = z2;

        const float4* s0 = (const float4*)(fm + ((size_t)(b * CC + c0)     ) * (HH * WW));
        const float4* s1 = (const float4*)(fm + ((size_t)(b * CC + c0 + 1)) * (HH * WW));
        for (int i = tid; i < 784; i += 256) {       // 784 float4 per channel
            float4 v0 = s0[i];
            float4 v1 = s1[i];
            int h = i / 14, w = (i % 14) * 4;
            float2* d = &fm_s[h * FSTRIDE + w];
            d[0] = make_float2(v0.x, v1.x);
            d[1] = make_float2(v0.y, v1.y);
            d[2] = make_float2(v0.z, v1.z);
            d[3] = make_float2(v0.w, v1.w);
        }
    }
    __syncthreads();

    const int wid  = tid >> 5;
    const int lane = tid & 31;
    float2* tmpw = tmp_s[wid];
    const char* tb  = (const char*)tmpw;
    const char* fmb = (const char*)fm_s;

    // stage-1 lane mapping: lanes 0..27 -> (hsub, qx)
    const int qx   = lane % 7;
    const int hsub = lane / 7;
    const bool act1 = (lane < 28);

    // stage-2 cell mapping: cell0 = lane, cell1 = lane+32
    const int p0 = lane / 7,        q0 = lane % 7;
    const int p1 = (lane + 32) / 7, q1 = (lane + 32) % 7;
    const bool has1 = (lane + 32 < 49);
    const int zb0 = ZROW * 7 + q0;
    const int zb1 = ZROW * 7 + q1;

    const int n = nbase + wid;

    float2 acc0 = make_float2(0.f, 0.f);
    float2 acc1 = make_float2(0.f, 0.f);

    #pragma unroll 1
    for (int j = 0; j < 9; j++) {
        const int r = b * R_PER_IMG + ((j == 0) ? n : (NN + n * 8 + (j - 1)));
        const float wroi = (j == 0) ? 1.0f : 0.125f;
        const int yinfo = __ldg(&g_yinfo[r]);
        const int ylo   = yinfo & 0xFF;
        const int span4 = yinfo >> 8;
        const int ky    = __ldg(&g_kmax[r * 2]);
        const int kx    = __ldg(&g_kmax[r * 2 + 1]);
        const int mbase = r * 16;
        const float* wbase = g_wgt + (size_t)r * 168;

        // ---- stage 1: x-interp. tmp[h][q] = sum_k wX[q][k]*fm[ylo+h][offx_q+k]
        {
            int metax = __ldg(&g_meta[mbase + 7 + qx]);
            int offx = metax & 0xFF, cntx = metax >> 8;
            int off8 = offx * 8;
            const float4* wx4 = (const float4*)(wbase + (7 + qx) * 12);
            float4 wa = __ldg(wx4);
            float4 wb = make_float4(0.f, 0.f, 0.f, 0.f);
            float4 wc = make_float4(0.f, 0.f, 0.f, 0.f);
            if (kx > 4) wb = __ldg(wx4 + 1);          // warp-uniform
            if (kx > 8) wc = __ldg(wx4 + 2);          // warp-uniform
            float w[12];
            w[0]=wa.x; w[1]=wa.y; w[2]=wa.z; w[3]=wa.w;
            w[4]=wb.x; w[5]=wb.y; w[6]=wb.z; w[7]=wb.w;
            w[8]=wc.x; w[9]=wc.y; w[10]=wc.z; w[11]=wc.w;
            #define CS1(K) case K: s1loop<K>(fmb, tmpw, ylo, span4, hsub, qx, act1, off8, cntx, w); break;
            switch (kx) {
                CS1(1) CS1(2) CS1(3) CS1(4) CS1(5) CS1(6)
                CS1(7) CS1(8) CS1(9) CS1(10) CS1(11)
                default: s1loop<12>(fmb, tmpw, ylo, span4, hsub, qx, act1, off8, cntx, w); break;
            }
            #undef CS1
        }
        __syncwarp();

        // ---- stage 2: y-interp. out[p][q] = sum_k wY[p][k]*tmp[offy_p-ylo+k][q]
        {
            int meta0 = __ldg(&g_meta[mbase + p0]);
            int meta1 = has1 ? __ldg(&g_meta[mbase + p1]) : meta0;
            const float4* wy40 = (const float4*)(wbase + p0 * 12);
            const float4* wy41 = (const float4*)(wbase + p1 * 12);
            float4 a0 = __ldg(wy40);
            float4 a1 = make_float4(0.f, 0.f, 0.f, 0.f);
            float4 a2 = make_float4(0.f, 0.f, 0.f, 0.f);
            float4 b0 = has1 ? __ldg(wy41) : make_float4(0.f, 0.f, 0.f, 0.f);
            float4 b1 = make_float4(0.f, 0.f, 0.f, 0.f);
            float4 b2 = make_float4(0.f, 0.f, 0.f, 0.f);
            if (ky > 4) { a1 = __ldg(wy40 + 1); if (has1) b1 = __ldg(wy41 + 1); }
            if (ky > 8) { a2 = __ldg(wy40 + 2); if (has1) b2 = __ldg(wy41 + 2); }
            float u0[12], u1c[12];
            u0[0]=a0.x; u0[1]=a0.y; u0[2]=a0.z; u0[3]=a0.w;
            u0[4]=a1.x; u0[5]=a1.y; u0[6]=a1.z; u0[7]=a1.w;
            u0[8]=a2.x; u0[9]=a2.y; u0[10]=a2.z; u0[11]=a2.w;
            u1c[0]=b0.x; u1c[1]=b0.y; u1c[2]=b0.z; u1c[3]=b0.w;
            u1c[4]=b1.x; u1c[5]=b1.y; u1c[6]=b1.z; u1c[7]=b1.w;
            u1c[8]=b2.x; u1c[9]=b2.y; u1c[10]=b2.z; u1c[11]=b2.w;

            int base0 = ((meta0 & 0xFF) - ylo) * 7 + q0, cnt0 = meta0 >> 8;
            int base1 = ((meta1 & 0xFF) - ylo) * 7 + q1, cnt1 = meta1 >> 8;

            float2 s0v, s1v;
            #define CS2(K) case K: { s0v = s2cell<K>(tb, base0, cnt0, zb0, u0); \
                s1v = has1 ? s2cell<K>(tb, base1, cnt1, zb1, u1c) : make_float2(0.f,0.f); } break;
            switch (ky) {
                CS2(1) CS2(2) CS2(3) CS2(4) CS2(5) CS2(6)
                CS2(7) CS2(8) CS2(9) CS2(10) CS2(11)
                default: { s0v = s2cell<12>(tb, base0, cnt0, zb0, u0);
                    s1v = has1 ? s2cell<12>(tb, base1, cnt1, zb1, u1c) : make_float2(0.f,0.f); } break;
            }
            #undef CS2
            acc0.x += wroi * s0v.x; acc0.y += wroi * s0v.y;
            acc1.x += wroi * s1v.x; acc1.y += wroi * s1v.y;
        }
        __syncwarp();   // tmp reuse safety before next roi
    }

    // ---- store out[b][n][c][p][q], channels c0 and c0+1 ----
    float* o = out + ((size_t)(b * NN + n) * CC + c0) * (PP * PP);
    o[lane]      = acc0.x;
    o[49 + lane] = acc0.y;
    if (has1) {
        o[lane + 32]      = acc1.x;
        o[49 + lane + 32] = acc1.y;
    }
}

// ---------------------------------------------------------------------------
extern "C" void kernel_launch(void* const* d_in, const int* in_sizes, int n_in,
                              void* d_out, int out_size) {
    const float* fm    = (const float*)d_in[0];
    const float* boxes = (const float*)d_in[1];
    const float* gts   = (const float*)d_in[2];
    float* out = (float*)d_out;

    prep_kernel<<<(R_TOTAL * 2 + 127) / 128, 128>>>(boxes, gts);

    dim3 grid(CC / 2, BB, 8);
    roi_main_kernel<<<grid, 256>>>(fm, out);
}

// round 10
// speedup vs baseline: 1.4175x; 1.2081x over previous
#include <cuda_runtime.h>
#include <cuda_bf16.h>
#include <cuda_fp16.h>

// Problem constants (fixed by dataset)
#define BB 2
#define CC 256
#define HH 56
#define WW 56
#define NN 64
#define MM 8
#define PP 7
#define R_PER_IMG (NN + NN*MM)        // 576
#define R_TOTAL   (BB * R_PER_IMG)    // 1152
#define MAXK 12

#define FSH     71                    // fm smem row stride in half2 (mod 32 == 7)
#define FROWB   (FSH * 4)             // row stride in bytes (284)
#define TROWS   64
#define ZCOL    60                    // zero column (half2 index) in every row
#define ZROW    63                    // zero row in tmp

// Per-roi tables.
// g_meta[r*16 + row], row 0..6 = y rows (p), 7..13 = x rows (q). meta = off | (cnt<<8)
// g_yinfo[r] = ylo | (span4<<8)
// g_kmax[r*2 + a] = warp-uniform EXACT max cnt for axis a (1..12)
// g_wgt[(r*14+row)*12 + k], zero-padded to 12 floats per row, 16B aligned
__device__ int   g_meta[R_TOTAL * 16];
__device__ int   g_yinfo[R_TOTAL];
__device__ int   g_kmax[R_TOTAL * 2];
__device__ __align__(16) float g_wgt[R_TOTAL * 14 * MAXK];

// ---------------------------------------------------------------------------
// Kernel A: build sparse interpolation tables for every roi & axis.
// One thread per (roi, axis). Replicates reference math exactly.
// ---------------------------------------------------------------------------
__global__ void prep_kernel(const float* __restrict__ boxes,
                            const float* __restrict__ gts) {
    int t = blockIdx.x * blockDim.x + threadIdx.x;
    if (t >= R_TOTAL * 2) return;
    int r = t >> 1, a = t & 1;
    int b = r / R_PER_IMG, idx = r % R_PER_IMG;

    float x1, y1, x2, y2;
    if (idx < NN) {
        const float* bx = boxes + (b * NN + idx) * 4;
        x1 = bx[0]; y1 = bx[1]; x2 = bx[2]; y2 = bx[3];
    } else {
        int n = (idx - NN) >> 3, m = (idx - NN) & 7;
        const float* bx = boxes + (b * NN + n) * 4;
        const float* gx = gts   + (b * MM + m) * 4;
        x1 = fminf(bx[0], gx[0]); y1 = fminf(bx[1], gx[1]);
        x2 = fmaxf(bx[2], gx[2]); y2 = fmaxf(bx[3], gx[3]);
    }

    float start = a ? x1 : y1;
    float len   = fmaxf(a ? (x2 - x1) : (y2 - y1), 1.0f);
    const float dimf = 56.0f;
    const int   dim  = 56;

    float bin = len / 7.0f;
    int   g   = (int)ceilf(bin);           // grid = ceil(length/P)
    float gf  = (float)g;
    float inv = 1.0f / gf;

    int lo_min = 1 << 20, hi_max = -1, cnt_max = 1;
    for (int p = 0; p < 7; p++) {
        float acc[MAXK];
        #pragma unroll
        for (int k = 0; k < MAXK; k++) acc[k] = 0.0f;
        int base = -1, hi = -1;
        float c0 = start + (float)p * bin;
        for (int s = 0; s < 8; s++) {
            if (s >= g) break;
            float coord = c0 + ((float)s + 0.5f) * bin / gf;
            if (!(coord >= -1.0f && coord <= dimf)) continue;
            float c = fmaxf(coord, 0.0f);
            int low = (int)floorf(c);
            int high; float cv;
            if (low >= dim - 1) { low = dim - 1; high = dim - 1; cv = (float)low; }
            else                { high = low + 1; cv = c; }
            float l  = cv - (float)low;
            float wl = (1.0f - l) * inv;
            float wh = l * inv;
            if (base < 0) base = low;
            int d  = low  - base;
            int d2 = high - base;
            if (d  >= 0 && d  < MAXK) acc[d]  += wl;
            if (d2 >= 0 && d2 < MAXK) acc[d2] += wh;
            if (high > hi) hi = high;
        }
        int cnt = (base < 0) ? 0 : (hi - base + 1);
        if (base < 0) base = 0;
        if (cnt > MAXK) cnt = MAXK;   // safety (true bound is 10)
        if (base < lo_min) lo_min = base;
        if (base + cnt > hi_max) hi_max = base + cnt;
        if (cnt > cnt_max) cnt_max = cnt;
        g_meta[r * 16 + a * 7 + p] = base | (cnt << 8);
        float* wp = g_wgt + (size_t)((r * 14 + a * 7 + p)) * MAXK;
        #pragma unroll
        for (int k = 0; k < MAXK; k++) wp[k] = acc[k];
    }
    if (cnt_max < 1)  cnt_max = 1;
    if (cnt_max > 12) cnt_max = 12;
    g_kmax[r * 2 + a] = cnt_max;           // exact, granularity 1
    if (a == 0) {
        int lo = lo_min, span = hi_max - lo_min;
        if (span < 1) { lo = 0; span = 1; }
        int span4 = (span + 3) & ~3;
        g_yinfo[r] = lo | (span4 << 8);
    }
}

// ---------------------------------------------------------------------------
// Stage bodies: templated on exact warp-uniform tap count KM, fully unrolled,
// branch-free; per-lane taps with k >= cnt redirected to a shared zero word
// (ZCOL / ZROW) via inline address select. Weights zero-padded.
// Stage-1 reads half2 (ch0,ch1) fm data -> 1 crossbar wavefront per tap.
// ---------------------------------------------------------------------------
template<int KM>
__device__ __forceinline__ void s1loop(const char* fmb, float2* tmpw,
        int ylo, int span4, int hsub, int qx, bool act1,
        int off4, int cntx, const float* w) {
    #pragma unroll 1
    for (int hb = 0; hb < span4; hb += 4) {
        if (act1) {
            int h = hb + hsub;
            const char* rowb = fmb + (ylo + h) * FROWB;
            float2 a = make_float2(0.f, 0.f);
            #pragma unroll
            for (int k = 0; k < KM; k++) {
                int ai = off4 + k * 4;
                if (k >= cntx) ai = ZCOL * 4;
                __half2 hv = *(const __half2*)(rowb + ai);
                float2 f = __half22float2(hv);
                a.x += w[k] * f.x; a.y += w[k] * f.y;
            }
            tmpw[h * 7 + qx] = a;
        }
    }
}

template<int KM>
__device__ __forceinline__ float2 s2cell(const char* tb, int base, int cnt,
                                         int zb, const float* u) {
    float2 s = make_float2(0.f, 0.f);
    #pragma unroll
    for (int k = 0; k < KM; k++) {
        int ai = base + k * 7;
        if (k >= cnt) ai = zb;
        float2 tv = *(const float2*)(tb + ai * 8);
        s.x += u[k] * tv.x; s.y += u[k] * tv.y;
    }
    return s;
}

// ---------------------------------------------------------------------------
// Kernel B: main compute. One CTA per (channel-pair, image, n-eighth).
// fm for 2 channels as half2 in smem (71-half2 row stride; mod-32==7 puts the
// 4 hsub rows on bank offsets {0,7,14,21}). Accumulation fp32; tmp fp32.
// 8 warps, one n each; per n: box roi + 8 ctx rois, 7x7 out in registers.
// ---------------------------------------------------------------------------
__global__ void __launch_bounds__(256, 3)
roi_main_kernel(const float* __restrict__ fm, float* __restrict__ out) {
    const int cp = blockIdx.x;          // channel pair: c0 = 2*cp
    const int b  = blockIdx.y;
    const int nbase = blockIdx.z * 8;   // 8 n per CTA, one per warp

    __shared__ __half2 fm_s[60 * FSH];          // 17040 B (rows 0..59)
    __shared__ float2  tmp_s[8][TROWS * 7];     // 28672 B

    const int tid = threadIdx.x;
    const int c0 = cp * 2;

    // ---- stage fm[b][c0..c0+1] as half2; zero pads ----
    {
        const __half2 zh = __floats2half2_rn(0.f, 0.f);
        // rows 56..59 fully zero (over-read h rows; includes their ZCOL)
        for (int i = tid; i < 4 * FSH; i += 256) fm_s[56 * FSH + i] = zh;
        // ZCOL zero in rows 0..55
        if (tid < 56) fm_s[tid * FSH + ZCOL] = zh;
        // tmp zero row (ZROW) for each warp
        if (tid < 56) tmp_s[tid / 7][ZROW * 7 + (tid % 7)] = make_float2(0.f, 0.f);

        const float4* s0 = (const float4*)(fm + ((size_t)(b * CC + c0)     ) * (HH * WW));
        const float4* s1 = (const float4*)(fm + ((size_t)(b * CC + c0 + 1)) * (HH * WW));
        for (int i = tid; i < 784; i += 256) {       // 784 float4 per channel
            float4 v0 = s0[i];
            float4 v1 = s1[i];
            int h = i / 14, w = (i % 14) * 4;
            __half2* d = &fm_s[h * FSH + w];
            d[0] = __floats2half2_rn(v0.x, v1.x);
            d[1] = __floats2half2_rn(v0.y, v1.y);
            d[2] = __floats2half2_rn(v0.z, v1.z);
            d[3] = __floats2half2_rn(v0.w, v1.w);
        }
    }
    __syncthreads();

    const int wid  = tid >> 5;
    const int lane = tid & 31;
    float2* tmpw = tmp_s[wid];
    const char* tb  = (const char*)tmpw;
    const char* fmb = (const char*)fm_s;

    // stage-1 lane mapping: lanes 0..27 -> (hsub, qx)
    const int qx   = lane % 7;
    const int hsub = lane / 7;
    const bool act1 = (lane < 28);

    // stage-2 cell mapping: cell0 = lane, cell1 = lane+32
    const int p0 = lane / 7,        q0 = lane % 7;
    const int p1 = (lane + 32) / 7, q1 = (lane + 32) % 7;
    const bool has1 = (lane + 32 < 49);
    const int zb0 = ZROW * 7 + q0;
    const int zb1 = ZROW * 7 + q1;

    const int n = nbase + wid;

    float2 acc0 = make_float2(0.f, 0.f);
    float2 acc1 = make_float2(0.f, 0.f);

    #pragma unroll 1
    for (int j = 0; j < 9; j++) {
        const int r = b * R_PER_IMG + ((j == 0) ? n : (NN + n * 8 + (j - 1)));
        const float wroi = (j == 0) ? 1.0f : 0.125f;
        const int yinfo = __ldg(&g_yinfo[r]);
        const int ylo   = yinfo & 0xFF;
        const int span4 = yinfo >> 8;
        const int ky    = __ldg(&g_kmax[r * 2]);
        const int kx    = __ldg(&g_kmax[r * 2 + 1]);
        const int mbase = r * 16;
        const float* wbase = g_wgt + (size_t)r * 168;

        // ---- stage 1: x-interp. tmp[h][q] = sum_k wX[q][k]*fm[ylo+h][offx_q+k]
        {
            int metax = __ldg(&g_meta[mbase + 7 + qx]);
            int offx = metax & 0xFF, cntx = metax >> 8;
            int off4 = offx * 4;
            const float4* wx4 = (const float4*)(wbase + (7 + qx) * 12);
            float4 wa = __ldg(wx4);
            float4 wb = make_float4(0.f, 0.f, 0.f, 0.f);
            float4 wc = make_float4(0.f, 0.f, 0.f, 0.f);
            if (kx > 4) wb = __ldg(wx4 + 1);          // warp-uniform
            if (kx > 8) wc = __ldg(wx4 + 2);          // warp-uniform
            float w[12];
            w[0]=wa.x; w[1]=wa.y; w[2]=wa.z; w[3]=wa.w;
            w[4]=wb.x; w[5]=wb.y; w[6]=wb.z; w[7]=wb.w;
            w[8]=wc.x; w[9]=wc.y; w[10]=wc.z; w[11]=wc.w;
            #define CS1(K) case K: s1loop<K>(fmb, tmpw, ylo, span4, hsub, qx, act1, off4, cntx, w); break;
            switch (kx) {
                CS1(1) CS1(2) CS1(3) CS1(4) CS1(5) CS1(6)
                CS1(7) CS1(8) CS1(9) CS1(10) CS1(11)
                default: s1loop<12>(fmb, tmpw, ylo, span4, hsub, qx, act1, off4, cntx, w); break;
            }
            #undef CS1
        }
        __syncwarp();

        // ---- stage 2: y-interp. out[p][q] = sum_k wY[p][k]*tmp[offy_p-ylo+k][q]
        {
            int meta0 = __ldg(&g_meta[mbase + p0]);
            int meta1 = has1 ? __ldg(&g_meta[mbase + p1]) : meta0;
            const float4* wy40 = (const float4*)(wbase + p0 * 12);
            const float4* wy41 = (const float4*)(wbase + p1 * 12);
            float4 a0 = __ldg(wy40);
            float4 a1 = make_float4(0.f, 0.f, 0.f, 0.f);
            float4 a2 = make_float4(0.f, 0.f, 0.f, 0.f);
            float4 b0 = has1 ? __ldg(wy41) : make_float4(0.f, 0.f, 0.f, 0.f);
            float4 b1 = make_float4(0.f, 0.f, 0.f, 0.f);
            float4 b2 = make_float4(0.f, 0.f, 0.f, 0.f);
            if (ky > 4) { a1 = __ldg(wy40 + 1); if (has1) b1 = __ldg(wy41 + 1); }
            if (ky > 8) { a2 = __ldg(wy40 + 2); if (has1) b2 = __ldg(wy41 + 2); }
            float u0[12], u1c[12];
            u0[0]=a0.x; u0[1]=a0.y; u0[2]=a0.z; u0[3]=a0.w;
            u0[4]=a1.x; u0[5]=a1.y; u0[6]=a1.z; u0[7]=a1.w;
            u0[8]=a2.x; u0[9]=a2.y; u0[10]=a2.z; u0[11]=a2.w;
            u1c[0]=b0.x; u1c[1]=b0.y; u1c[2]=b0.z; u1c[3]=b0.w;
            u1c[4]=b1.x; u1c[5]=b1.y; u1c[6]=b1.z; u1c[7]=b1.w;
            u1c[8]=b2.x; u1c[9]=b2.y; u1c[10]=b2.z; u1c[11]=b2.w;

            int base0 = ((meta0 & 0xFF) - ylo) * 7 + q0, cnt0 = meta0 >> 8;
            int base1 = ((meta1 & 0xFF) - ylo) * 7 + q1, cnt1 = meta1 >> 8;

            float2 s0v, s1v;
            #define CS2(K) case K: { s0v = s2cell<K>(tb, base0, cnt0, zb0, u0); \
                s1v = has1 ? s2cell<K>(tb, base1, cnt1, zb1, u1c) : make_float2(0.f,0.f); } break;
            switch (ky) {
                CS2(1) CS2(2) CS2(3) CS2(4) CS2(5) CS2(6)
                CS2(7) CS2(8) CS2(9) CS2(10) CS2(11)
                default: { s0v = s2cell<12>(tb, base0, cnt0, zb0, u0);
                    s1v = has1 ? s2cell<12>(tb, base1, cnt1, zb1, u1c) : make_float2(0.f,0.f); } break;
            }
            #undef CS2
            acc0.x += wroi * s0v.x; acc0.y += wroi * s0v.y;
            acc1.x += wroi * s1v.x; acc1.y += wroi * s1v.y;
        }
        __syncwarp();   // tmp reuse safety before next roi
    }

    // ---- store out[b][n][c][p][q], channels c0 and c0+1 ----
    float* o = out + ((size_t)(b * NN + n) * CC + c0) * (PP * PP);
    o[lane]      = acc0.x;
    o[49 + lane] = acc0.y;
    if (has1) {
        o[lane + 32]      = acc1.x;
        o[49 + lane + 32] = acc1.y;
    }
}

// ---------------------------------------------------------------------------
extern "C" void kernel_launch(void* const* d_in, const int* in_sizes, int n_in,
                              void* d_out, int out_size) {
    const float* fm    = (const float*)d_in[0];
    const float* boxes = (const float*)d_in[1];
    const float* gts   = (const float*)d_in[2];
    float* out = (float*)d_out;

    prep_kernel<<<(R_TOTAL * 2 + 127) / 128, 128>>>(boxes, gts);

    dim3 grid(CC / 2, BB, 8);
    roi_main_kernel<<<grid, 256>>>(fm, out);
}

// round 11
// speedup vs baseline: 1.7334x; 1.2228x over previous
#include <cuda_runtime.h>
#include <cuda_bf16.h>
#include <cuda_fp16.h>

// Problem constants (fixed by dataset)
#define BB 2
#define CC 256
#define HH 56
#define WW 56
#define NN 64
#define MM 8
#define PP 7
#define R_PER_IMG (NN + NN*MM)        // 576
#define R_TOTAL   (BB * R_PER_IMG)    // 1152
#define MAXK 12

#define FS      71                    // fm smem row stride in uint2 (4ch fp16)
#define FROWB   (FS * 8)              // row stride in bytes (568)
#define TROWS   64
#define ZCOL    60                    // zero column (uint2 index) in every row
#define ZROW    63                    // zero row in tmp

// Per-roi tables.
// g_meta[r*16 + row], row 0..6 = y rows (p), 7..13 = x rows (q). meta = off | (cnt<<8)
// g_yinfo[r] = ylo | (span4<<8)
// g_kmax[r*2 + a] = warp-uniform EXACT max cnt for axis a (1..12)
// g_wgt[(r*14+row)*12 + k], zero-padded to 12 floats per row, 16B aligned
__device__ int   g_meta[R_TOTAL * 16];
__device__ int   g_yinfo[R_TOTAL];
__device__ int   g_kmax[R_TOTAL * 2];
__device__ __align__(16) float g_wgt[R_TOTAL * 14 * MAXK];

// ---------------------------------------------------------------------------
// Kernel A: build sparse interpolation tables for every roi & axis.
// One thread per (roi, axis). Replicates reference math exactly.
// ---------------------------------------------------------------------------
__global__ void prep_kernel(const float* __restrict__ boxes,
                            const float* __restrict__ gts) {
    int t = blockIdx.x * blockDim.x + threadIdx.x;
    if (t >= R_TOTAL * 2) return;
    int r = t >> 1, a = t & 1;
    int b = r / R_PER_IMG, idx = r % R_PER_IMG;

    float x1, y1, x2, y2;
    if (idx < NN) {
        const float* bx = boxes + (b * NN + idx) * 4;
        x1 = bx[0]; y1 = bx[1]; x2 = bx[2]; y2 = bx[3];
    } else {
        int n = (idx - NN) >> 3, m = (idx - NN) & 7;
        const float* bx = boxes + (b * NN + n) * 4;
        const float* gx = gts   + (b * MM + m) * 4;
        x1 = fminf(bx[0], gx[0]); y1 = fminf(bx[1], gx[1]);
        x2 = fmaxf(bx[2], gx[2]); y2 = fmaxf(bx[3], gx[3]);
    }

    float start = a ? x1 : y1;
    float len   = fmaxf(a ? (x2 - x1) : (y2 - y1), 1.0f);
    const float dimf = 56.0f;
    const int   dim  = 56;

    float bin = len / 7.0f;
    int   g   = (int)ceilf(bin);           // grid = ceil(length/P)
    float gf  = (float)g;
    float inv = 1.0f / gf;

    int lo_min = 1 << 20, hi_max = -1, cnt_max = 1;
    for (int p = 0; p < 7; p++) {
        float acc[MAXK];
        #pragma unroll
        for (int k = 0; k < MAXK; k++) acc[k] = 0.0f;
        int base = -1, hi = -1;
        float c0 = start + (float)p * bin;
        for (int s = 0; s < 8; s++) {
            if (s >= g) break;
            float coord = c0 + ((float)s + 0.5f) * bin / gf;
            if (!(coord >= -1.0f && coord <= dimf)) continue;
            float c = fmaxf(coord, 0.0f);
            int low = (int)floorf(c);
            int high; float cv;
            if (low >= dim - 1) { low = dim - 1; high = dim - 1; cv = (float)low; }
            else                { high = low + 1; cv = c; }
            float l  = cv - (float)low;
            float wl = (1.0f - l) * inv;
            float wh = l * inv;
            if (base < 0) base = low;
            int d  = low  - base;
            int d2 = high - base;
            if (d  >= 0 && d  < MAXK) acc[d]  += wl;
            if (d2 >= 0 && d2 < MAXK) acc[d2] += wh;
            if (high > hi) hi = high;
        }
        int cnt = (base < 0) ? 0 : (hi - base + 1);
        if (base < 0) base = 0;
        if (cnt > MAXK) cnt = MAXK;   // safety (true bound is 10)
        if (base < lo_min) lo_min = base;
        if (base + cnt > hi_max) hi_max = base + cnt;
        if (cnt > cnt_max) cnt_max = cnt;
        g_meta[r * 16 + a * 7 + p] = base | (cnt << 8);
        float* wp = g_wgt + (size_t)((r * 14 + a * 7 + p)) * MAXK;
        #pragma unroll
        for (int k = 0; k < MAXK; k++) wp[k] = acc[k];
    }
    if (cnt_max < 1)  cnt_max = 1;
    if (cnt_max > 12) cnt_max = 12;
    g_kmax[r * 2 + a] = cnt_max;           // exact, granularity 1
    if (a == 0) {
        int lo = lo_min, span = hi_max - lo_min;
        if (span < 1) { lo = 0; span = 1; }
        int span4 = (span + 3) & ~3;
        g_yinfo[r] = lo | (span4 << 8);
    }
}

// ---------------------------------------------------------------------------
// Helpers: pack 4 floats into uint2 of two half2s; unpack to two float2.
// ---------------------------------------------------------------------------
__device__ __forceinline__ uint2 pack4h(float a, float b, float c, float d) {
    __half2 h01 = __floats2half2_rn(a, b);
    __half2 h23 = __floats2half2_rn(c, d);
    uint2 r;
    r.x = *reinterpret_cast<unsigned*>(&h01);
    r.y = *reinterpret_cast<unsigned*>(&h23);
    return r;
}

// ---------------------------------------------------------------------------
// Stage bodies: templated on exact warp-uniform tap count KM, fully unrolled,
// branch-free; per-lane taps with k >= cnt redirected to a shared zero word
// (ZCOL / ZROW) via inline address select. Weights zero-padded; the weight
// float4s needed are selected at COMPILE TIME by KM (exact LDG bytes, no
// pre-switch register arrays).
// Data plane fp16 x 4 channels (uint2); accumulation fp32.
// ---------------------------------------------------------------------------
template<int KM>
__device__ __forceinline__ void s1loop(const char* fmb, uint2* tmpw,
        int ylo, int span4, int hsub, int qx, bool act1,
        int offb, int cntx, const float* wp) {
    const float4* w4 = (const float4*)wp;
    float4 wa = __ldg(w4);
    float4 wb = (KM > 4) ? __ldg(w4 + 1) : make_float4(0.f, 0.f, 0.f, 0.f);
    float4 wc = (KM > 8) ? __ldg(w4 + 2) : make_float4(0.f, 0.f, 0.f, 0.f);
    float w[12];
    w[0]=wa.x; w[1]=wa.y; w[2]=wa.z; w[3]=wa.w;
    w[4]=wb.x; w[5]=wb.y; w[6]=wb.z; w[7]=wb.w;
    w[8]=wc.x; w[9]=wc.y; w[10]=wc.z; w[11]=wc.w;
    #pragma unroll 1
    for (int hb = 0; hb < span4; hb += 4) {
        if (act1) {
            int h = hb + hsub;
            const char* rowb = fmb + (ylo + h) * FROWB;
            float2 a01 = make_float2(0.f, 0.f);
            float2 a23 = make_float2(0.f, 0.f);
            #pragma unroll
            for (int k = 0; k < KM; k++) {
                int ai = offb + k * 8;
                if (k >= cntx) ai = ZCOL * 8;
                uint2 hv = *(const uint2*)(rowb + ai);
                float2 f01 = __half22float2(*reinterpret_cast<__half2*>(&hv.x));
                float2 f23 = __half22float2(*reinterpret_cast<__half2*>(&hv.y));
                a01.x += w[k] * f01.x; a01.y += w[k] * f01.y;
                a23.x += w[k] * f23.x; a23.y += w[k] * f23.y;
            }
            tmpw[h * 7 + qx] = pack4h(a01.x, a01.y, a23.x, a23.y);
        }
    }
}

template<int KM>
__device__ __forceinline__ float4 s2cell(const char* tb, int base, int cnt,
                                         int zb, const float* wp) {
    const float4* w4 = (const float4*)wp;
    float4 ua = __ldg(w4);
    float4 ub = (KM > 4) ? __ldg(w4 + 1) : make_float4(0.f, 0.f, 0.f, 0.f);
    float4 uc = (KM > 8) ? __ldg(w4 + 2) : make_float4(0.f, 0.f, 0.f, 0.f);
    float u[12];
    u[0]=ua.x; u[1]=ua.y; u[2]=ua.z; u[3]=ua.w;
    u[4]=ub.x; u[5]=ub.y; u[6]=ub.z; u[7]=ub.w;
    u[8]=uc.x; u[9]=uc.y; u[10]=uc.z; u[11]=uc.w;
    float4 s = make_float4(0.f, 0.f, 0.f, 0.f);
    #pragma unroll
    for (int k = 0; k < KM; k++) {
        int ai = base + k * 7;
        if (k >= cnt) ai = zb;
        uint2 tv = *(const uint2*)(tb + ai * 8);
        float2 t01 = __half22float2(*reinterpret_cast<__half2*>(&tv.x));
        float2 t23 = __half22float2(*reinterpret_cast<__half2*>(&tv.y));
        s.x += u[k] * t01.x; s.y += u[k] * t01.y;
        s.z += u[k] * t23.x; s.w += u[k] * t23.y;
    }
    return s;
}

// ---------------------------------------------------------------------------
// Kernel B: main compute. One CTA per (channel-quad, image, n-eighth).
// fm for 4 channels as uint2(2x half2) in smem; tmp likewise fp16 4ch.
// 8 warps, one n each; per n: box roi + 8 ctx rois, 7x7x4ch out in registers.
// ---------------------------------------------------------------------------
__global__ void __launch_bounds__(256, 3)
roi_main_kernel(const float* __restrict__ fm, float* __restrict__ out) {
    const int cq = blockIdx.x;          // channel quad: c0 = 4*cq
    const int b  = blockIdx.y;
    const int nbase = blockIdx.z * 8;   // 8 n per CTA, one per warp

    __shared__ uint2 fm_s[60 * FS];            // 34080 B (rows 0..59)
    __shared__ uint2 tmp_s[8][TROWS * 7];      // 28672 B

    const int tid = threadIdx.x;
    const int c0 = cq * 4;

    // ---- stage fm[b][c0..c0+3] as packed fp16; zero pads ----
    {
        const uint2 z2 = make_uint2(0u, 0u);
        for (int i = tid; i < 4 * FS; i += 256) fm_s[56 * FS + i] = z2;   // rows 56..59
        if (tid < 56) fm_s[tid * FS + ZCOL] = z2;                         // zero col
        if (tid < 56) tmp_s[tid / 7][ZROW * 7 + (tid % 7)] = z2;          // tmp zero row

        const float4* s0 = (const float4*)(fm + ((size_t)(b * CC + c0)     ) * (HH * WW));
        const float4* s1 = (const float4*)(fm + ((size_t)(b * CC + c0 + 1)) * (HH * WW));
        const float4* s2 = (const float4*)(fm + ((size_t)(b * CC + c0 + 2)) * (HH * WW));
        const float4* s3 = (const float4*)(fm + ((size_t)(b * CC + c0 + 3)) * (HH * WW));
        for (int i = tid; i < 784; i += 256) {       // 784 float4 per channel
            float4 v0 = s0[i];
            float4 v1 = s1[i];
            float4 v2 = s2[i];
            float4 v3 = s3[i];
            int h = i / 14, w = (i % 14) * 4;
            uint2* d = &fm_s[h * FS + w];
            d[0] = pack4h(v0.x, v1.x, v2.x, v3.x);
            d[1] = pack4h(v0.y, v1.y, v2.y, v3.y);
            d[2] = pack4h(v0.z, v1.z, v2.z, v3.z);
            d[3] = pack4h(v0.w, v1.w, v2.w, v3.w);
        }
    }
    __syncthreads();

    const int wid  = tid >> 5;
    const int lane = tid & 31;
    uint2* tmpw = tmp_s[wid];
    const char* tb  = (const char*)tmpw;
    const char* fmb = (const char*)fm_s;

    // stage-1 lane mapping: lanes 0..27 -> (hsub, qx)
    const int qx   = lane % 7;
    const int hsub = lane / 7;
    const bool act1 = (lane < 28);

    // stage-2 cell mapping: cell0 = lane, cell1 = lane+32
    const int p0 = lane / 7,        q0 = lane % 7;
    const int p1 = (lane + 32) / 7, q1 = (lane + 32) % 7;
    const bool has1 = (lane + 32 < 49);
    const int zb0 = ZROW * 7 + q0;
    const int zb1 = ZROW * 7 + q1;

    const int n = nbase + wid;

    float4 acc0 = make_float4(0.f, 0.f, 0.f, 0.f);
    float4 acc1 = make_float4(0.f, 0.f, 0.f, 0.f);

    #pragma unroll 1
    for (int j = 0; j < 9; j++) {
        const int r = b * R_PER_IMG + ((j == 0) ? n : (NN + n * 8 + (j - 1)));
        const float wroi = (j == 0) ? 1.0f : 0.125f;
        const int yinfo = __ldg(&g_yinfo[r]);
        const int ylo   = yinfo & 0xFF;
        const int span4 = yinfo >> 8;
        const int ky    = __ldg(&g_kmax[r * 2]);
        const int kx    = __ldg(&g_kmax[r * 2 + 1]);
        const int mbase = r * 16;
        const float* wbase = g_wgt + (size_t)r * 168;

        // ---- stage 1: x-interp. tmp[h][q] = sum_k wX[q][k]*fm[ylo+h][offx_q+k]
        {
            int metax = __ldg(&g_meta[mbase + 7 + qx]);
            int offx = metax & 0xFF, cntx = metax >> 8;
            int offb = offx * 8;
            const float* wpx = wbase + (7 + qx) * 12;
            #define CS1(K) case K: s1loop<K>(fmb, tmpw, ylo, span4, hsub, qx, act1, offb, cntx, wpx); break;
            switch (kx) {
                CS1(1) CS1(2) CS1(3) CS1(4) CS1(5) CS1(6)
                CS1(7) CS1(8) CS1(9) CS1(10) CS1(11)
                default: s1loop<12>(fmb, tmpw, ylo, span4, hsub, qx, act1, offb, cntx, wpx); break;
            }
            #undef CS1
        }
        __syncwarp();

        // ---- stage 2: y-interp. out[p][q] = sum_k wY[p][k]*tmp[offy_p-ylo+k][q]
        {
            int meta0 = __ldg(&g_meta[mbase + p0]);
            int meta1 = has1 ? __ldg(&g_meta[mbase + p1]) : meta0;
            int base0 = ((meta0 & 0xFF) - ylo) * 7 + q0, cnt0 = meta0 >> 8;
            int base1 = ((meta1 & 0xFF) - ylo) * 7 + q1, cnt1 = meta1 >> 8;
            const float* wp0 = wbase + p0 * 12;
            const float* wp1 = wbase + p1 * 12;

            float4 s0v, s1v;
            #define CS2(K) case K: { s0v = s2cell<K>(tb, base0, cnt0, zb0, wp0); \
                s1v = has1 ? s2cell<K>(tb, base1, cnt1, zb1, wp1) : make_float4(0.f,0.f,0.f,0.f); } break;
            switch (ky) {
                CS2(1) CS2(2) CS2(3) CS2(4) CS2(5) CS2(6)
                CS2(7) CS2(8) CS2(9) CS2(10) CS2(11)
                default: { s0v = s2cell<12>(tb, base0, cnt0, zb0, wp0);
                    s1v = has1 ? s2cell<12>(tb, base1, cnt1, zb1, wp1) : make_float4(0.f,0.f,0.f,0.f); } break;
            }
            #undef CS2
            acc0.x += wroi * s0v.x; acc0.y += wroi * s0v.y;
            acc0.z += wroi * s0v.z; acc0.w += wroi * s0v.w;
            acc1.x += wroi * s1v.x; acc1.y += wroi * s1v.y;
            acc1.z += wroi * s1v.z; acc1.w += wroi * s1v.w;
        }
        __syncwarp();   // tmp reuse safety before next roi
    }

    // ---- store out[b][n][c][p][q], channels c0..c0+3 ----
    float* o = out + ((size_t)(b * NN + n) * CC + c0) * (PP * PP);
    o[lane]       = acc0.x;
    o[49 + lane]  = acc0.y;
    o[98 + lane]  = acc0.z;
    o[147 + lane] = acc0.w;
    if (has1) {
        o[lane + 32]       = acc1.x;
        o[49 + lane + 32]  = acc1.y;
        o[98 + lane + 32]  = acc1.z;
        o[147 + lane + 32] = acc1.w;
    }
}

// ---------------------------------------------------------------------------
extern "C" void kernel_launch(void* const* d_in, const int* in_sizes, int n_in,
                              void* d_out, int out_size) {
    const float* fm    = (const float*)d_in[0];
    const float* boxes = (const float*)d_in[1];
    const float* gts   = (const float*)d_in[2];
    float* out = (float*)d_out;

    prep_kernel<<<(R_TOTAL * 2 + 127) / 128, 128>>>(boxes, gts);

    dim3 grid(CC / 4, BB, 8);
    roi_main_kernel<<<grid, 256>>>(fm, out);
}

// round 12
// speedup vs baseline: 1.7591x; 1.0148x over previous
#include <cuda_runtime.h>
#include <cuda_bf16.h>
#include <cuda_fp16.h>

// Problem constants (fixed by dataset)
#define BB 2
#define CC 256
#define HH 56
#define WW 56
#define NN 64
#define MM 8
#define PP 7
#define R_PER_IMG (NN + NN*MM)        // 576
#define R_TOTAL   (BB * R_PER_IMG)    // 1152
#define MAXK 12
#define KCAP 10                       // true max support count (bin<=7.92 -> cnt<=10)

#define FS      71                    // fm smem row stride in uint2 (4ch fp16)
#define FROWB   (FS * 8)              // row stride in bytes
#define TROWS   66                    // tmp rows (worst read row index 64)

// Per-roi tables.
// g_meta[r*16 + row], rows 0..6 = y (p), 7..13 = x (q). meta = off | (cnt<<8)
// g_yinfo[r] = ylo | (span4<<8)
// g_kmax[r*2 + a] = warp-uniform EXACT max cnt for axis a (1..10)
// g_wgt[(r*14+row)*12 + k], zero-padded to 12 floats per row, 16B aligned
__device__ int   g_meta[R_TOTAL * 16];
__device__ int   g_yinfo[R_TOTAL];
__device__ int   g_kmax[R_TOTAL * 2];
__device__ __align__(16) float g_wgt[R_TOTAL * 14 * MAXK];

// ---------------------------------------------------------------------------
// Kernel A: build sparse interpolation tables. Reference math exactly.
// ---------------------------------------------------------------------------
__global__ void prep_kernel(const float* __restrict__ boxes,
                            const float* __restrict__ gts) {
    int t = blockIdx.x * blockDim.x + threadIdx.x;
    if (t >= R_TOTAL * 2) return;
    int r = t >> 1, a = t & 1;
    int b = r / R_PER_IMG, idx = r % R_PER_IMG;

    float x1, y1, x2, y2;
    if (idx < NN) {
        const float* bx = boxes + (b * NN + idx) * 4;
        x1 = bx[0]; y1 = bx[1]; x2 = bx[2]; y2 = bx[3];
    } else {
        int n = (idx - NN) >> 3, m = (idx - NN) & 7;
        const float* bx = boxes + (b * NN + n) * 4;
        const float* gx = gts   + (b * MM + m) * 4;
        x1 = fminf(bx[0], gx[0]); y1 = fminf(bx[1], gx[1]);
        x2 = fmaxf(bx[2], gx[2]); y2 = fmaxf(bx[3], gx[3]);
    }

    float start = a ? x1 : y1;
    float len   = fmaxf(a ? (x2 - x1) : (y2 - y1), 1.0f);
    const float dimf = 56.0f;
    const int   dim  = 56;

    float bin = len / 7.0f;
    int   g   = (int)ceilf(bin);
    float gf  = (float)g;
    float inv = 1.0f / gf;

    int lo_min = 1 << 20, hi_max = -1, cnt_max = 1;
    for (int p = 0; p < 7; p++) {
        float acc[MAXK];
        #pragma unroll
        for (int k = 0; k < MAXK; k++) acc[k] = 0.0f;
        int base = -1, hi = -1;
        float c0 = start + (float)p * bin;
        for (int s = 0; s < 8; s++) {
            if (s >= g) break;
            float coord = c0 + ((float)s + 0.5f) * bin / gf;
            if (!(coord >= -1.0f && coord <= dimf)) continue;
            float c = fmaxf(coord, 0.0f);
            int low = (int)floorf(c);
            int high; float cv;
            if (low >= dim - 1) { low = dim - 1; high = dim - 1; cv = (float)low; }
            else                { high = low + 1; cv = c; }
            float l  = cv - (float)low;
            float wl = (1.0f - l) * inv;
            float wh = l * inv;
            if (base < 0) base = low;
            int d  = low  - base;
            int d2 = high - base;
            if (d  >= 0 && d  < MAXK) acc[d]  += wl;
            if (d2 >= 0 && d2 < MAXK) acc[d2] += wh;
            if (high > hi) hi = high;
        }
        int cnt = (base < 0) ? 0 : (hi - base + 1);
        if (base < 0) base = 0;
        if (cnt > KCAP) cnt = KCAP;   // true bound is 10
        if (base < lo_min) lo_min = base;
        if (base + cnt > hi_max) hi_max = base + cnt;
        if (cnt > cnt_max) cnt_max = cnt;
        g_meta[r * 16 + a * 7 + p] = base | (cnt << 8);
        float* wp = g_wgt + (size_t)((r * 14 + a * 7 + p)) * MAXK;
        #pragma unroll
        for (int k = 0; k < MAXK; k++) wp[k] = acc[k];
    }
    if (cnt_max < 1)    cnt_max = 1;
    if (cnt_max > KCAP) cnt_max = KCAP;
    g_kmax[r * 2 + a] = cnt_max;
    if (a == 0) {
        int lo = lo_min, span = hi_max - lo_min;
        if (span < 1) { lo = 0; span = 1; }
        int span4 = (span + 3) & ~3;
        g_yinfo[r] = lo | (span4 << 8);
    }
}

// ---------------------------------------------------------------------------
// Zero-init output (each cell receives exactly two atomicAdd contributions).
// ---------------------------------------------------------------------------
__global__ void zero_out_kernel(float4* __restrict__ o) {
    o[blockIdx.x * 256 + threadIdx.x] = make_float4(0.f, 0.f, 0.f, 0.f);
}

// ---------------------------------------------------------------------------
// Packed fp32x2 helpers (FFMA2) + half2 -> packed float2 conversion.
// ---------------------------------------------------------------------------
typedef unsigned long long u64;

__device__ __forceinline__ u64 h2f2(unsigned hv) {
    u64 r;
    asm("{.reg .b16 lo16, hi16; .reg .f32 flo, fhi;\n\t"
        "mov.b32 {lo16, hi16}, %1;\n\t"
        "cvt.f32.f16 flo, lo16;\n\t"
        "cvt.f32.f16 fhi, hi16;\n\t"
        "mov.b64 %0, {flo, fhi};}\n\t" : "=l"(r) : "r"(hv));
    return r;
}
__device__ __forceinline__ u64 bcast2(float w) {
    u64 r; asm("mov.b64 %0, {%1, %1};" : "=l"(r) : "f"(w)); return r;
}
__device__ __forceinline__ void fma2(u64& d, u64 a, u64 b) {
    asm("fma.rn.f32x2 %0, %1, %2, %3;" : "=l"(d) : "l"(a), "l"(b), "l"(d));
}
__device__ __forceinline__ float2 up2(u64 v) {
    float2 f; asm("mov.b64 {%0, %1}, %2;" : "=f"(f.x), "=f"(f.y) : "l"(v)); return f;
}
__device__ __forceinline__ uint2 pack4h(float a, float b, float c, float d) {
    __half2 h01 = __floats2half2_rn(a, b);
    __half2 h23 = __floats2half2_rn(c, d);
    uint2 r;
    r.x = *reinterpret_cast<unsigned*>(&h01);
    r.y = *reinterpret_cast<unsigned*>(&h23);
    return r;
}
__device__ __forceinline__ float fcomp(float4 v, int i) {
    return i == 0 ? v.x : i == 1 ? v.y : i == 2 ? v.z : v.w;
}

// ---------------------------------------------------------------------------
// Stage bodies. All masking is done by zero-padded WEIGHTS: over-read taps
// multiply finite garbage-free data (fm pad cols zeroed; tmp zero-initialized,
// thereafter always finite fp16) by 0.0 -> plain LDS with immediate offsets,
// no selects. KM = exact warp-uniform max cnt (<=10).
// ---------------------------------------------------------------------------
template<int KM>
__device__ __forceinline__ void s1loop(const char* fmb, uint2* tmpw,
        int ylo, int span4, int hsub, int qx, bool act1,
        int offu, const float* wp) {
    const float4* w4 = (const float4*)wp;
    float4 wa = __ldg(w4);
    float4 wb = (KM > 4) ? __ldg(w4 + 1) : make_float4(0.f, 0.f, 0.f, 0.f);
    float4 wc = (KM > 8) ? __ldg(w4 + 2) : make_float4(0.f, 0.f, 0.f, 0.f);
    u64 w2[KM];
    #pragma unroll
    for (int k = 0; k < KM; k++) {
        float wk = (k < 4) ? fcomp(wa, k) : (k < 8) ? fcomp(wb, k - 4) : fcomp(wc, k - 8);
        w2[k] = bcast2(wk);
    }
    #pragma unroll 1
    for (int hb = 0; hb < span4; hb += 4) {
        if (act1) {
            int h = hb + hsub;
            const uint2* row = (const uint2*)(fmb + (ylo + h) * FROWB) + offu;
            u64 a01 = 0, a23 = 0;   // bits 0 == {+0.f,+0.f}
            #pragma unroll
            for (int k = 0; k < KM; k++) {
                uint2 hv = row[k];
                fma2(a01, w2[k], h2f2(hv.x));
                fma2(a23, w2[k], h2f2(hv.y));
            }
            float2 f01 = up2(a01), f23 = up2(a23);
            tmpw[h * 7 + qx] = pack4h(f01.x, f01.y, f23.x, f23.y);
        }
    }
}

template<int KM>
__device__ __forceinline__ void s2cell(const char* tb, int basei,
                                       const float* wp, u64& s01, u64& s23) {
    const float4* w4 = (const float4*)wp;
    float4 ua = __ldg(w4);
    float4 ub = (KM > 4) ? __ldg(w4 + 1) : make_float4(0.f, 0.f, 0.f, 0.f);
    float4 uc = (KM > 8) ? __ldg(w4 + 2) : make_float4(0.f, 0.f, 0.f, 0.f);
    s01 = 0; s23 = 0;
    #pragma unroll
    for (int k = 0; k < KM; k++) {
        float wk = (k < 4) ? fcomp(ua, k) : (k < 8) ? fcomp(ub, k - 4) : fcomp(uc, k - 8);
        u64 w2 = bcast2(wk);
        uint2 tv = *(const uint2*)(tb + (basei + k * 7) * 8);
        fma2(s01, w2, h2f2(tv.x));
        fma2(s23, w2, h2f2(tv.y));
    }
}

// ---------------------------------------------------------------------------
// Kernel B: one CTA per (channel-quad, image, n-chunk, j-half). Each output
// cell gets exactly TWO atomicAdd contributions (j 0..4 and j 5..8 halves) --
// commutative fp32, deterministic. fm 4ch fp16 packed in smem, pad columns
// zeroed; tmp fp16, zero-initialized once. 8 warps, one n each.
// ---------------------------------------------------------------------------
__global__ void __launch_bounds__(256, 3)
roi_main_kernel(const float* __restrict__ fm, float* __restrict__ out) {
    const int cq = blockIdx.x;               // channel quad: c0 = 4*cq
    const int b  = blockIdx.y;
    const int nchunk = blockIdx.z >> 1;
    const int jhalf  = blockIdx.z & 1;
    const int nbase  = nchunk * 8;

    __shared__ uint2 fm_s[60 * FS];          // 34080 B
    __shared__ uint2 tmp_s[8][TROWS * 7];    // 29568 B

    const int tid = threadIdx.x;
    const int c0 = cq * 4;

    // ---- stage fm[b][c0..c0+3] packed fp16; zero ALL pad regions + tmp ----
    {
        const uint2 z2 = make_uint2(0u, 0u);
        for (int i = tid; i < 4 * FS; i += 256) fm_s[56 * FS + i] = z2;   // rows 56..59
        for (int i = tid; i < 56 * 15; i += 256) {                        // cols 56..70
            int h = i / 15, w = 56 + (i % 15);
            fm_s[h * FS + w] = z2;
        }
        uint2* tz = &tmp_s[0][0];
        for (int i = tid; i < 8 * TROWS * 7; i += 256) tz[i] = z2;        // tmp finite

        const float4* s0 = (const float4*)(fm + ((size_t)(b * CC + c0)     ) * (HH * WW));
        const float4* s1 = (const float4*)(fm + ((size_t)(b * CC + c0 + 1)) * (HH * WW));
        const float4* s2 = (const float4*)(fm + ((size_t)(b * CC + c0 + 2)) * (HH * WW));
        const float4* s3 = (const float4*)(fm + ((size_t)(b * CC + c0 + 3)) * (HH * WW));
        for (int i = tid; i < 784; i += 256) {
            float4 v0 = s0[i];
            float4 v1 = s1[i];
            float4 v2 = s2[i];
            float4 v3 = s3[i];
            int h = i / 14, w = (i % 14) * 4;
            uint2* d = &fm_s[h * FS + w];
            d[0] = pack4h(v0.x, v1.x, v2.x, v3.x);
            d[1] = pack4h(v0.y, v1.y, v2.y, v3.y);
            d[2] = pack4h(v0.z, v1.z, v2.z, v3.z);
            d[3] = pack4h(v0.w, v1.w, v2.w, v3.w);
        }
    }
    __syncthreads();

    const int wid  = tid >> 5;
    const int lane = tid & 31;
    uint2* tmpw = tmp_s[wid];
    const char* tb  = (const char*)tmpw;
    const char* fmb = (const char*)fm_s;

    // stage-1 lane mapping: lanes 0..27 -> (hsub, qx)
    const int qx   = lane % 7;
    const int hsub = lane / 7;
    const bool act1 = (lane < 28);

    // stage-2 cell mapping: cell0 = lane, cell1 = lane+32
    const int p0 = lane / 7,        q0 = lane % 7;
    const int p1 = (lane + 32) / 7, q1 = (lane + 32) % 7;
    const bool has1 = (lane + 32 < 49);

    const int n = nbase + wid;

    u64 acc001 = 0, acc023 = 0;   // cell0, ch01 / ch23
    u64 acc101 = 0, acc123 = 0;   // cell1

    const int jlo = jhalf ? 5 : 0;
    const int jhi = jhalf ? 9 : 5;

    #pragma unroll 1
    for (int j = jlo; j < jhi; j++) {
        const int r = b * R_PER_IMG + ((j == 0) ? n : (NN + n * 8 + (j - 1)));
        const u64 wroi2 = bcast2((j == 0) ? 1.0f : 0.125f);
        const int yinfo = __ldg(&g_yinfo[r]);
        const int ylo   = yinfo & 0xFF;
        const int span4 = yinfo >> 8;
        const int ky    = __ldg(&g_kmax[r * 2]);
        const int kx    = __ldg(&g_kmax[r * 2 + 1]);
        const int mbase = r * 16;
        const float* wbase = g_wgt + (size_t)r * 168;

        // ---- stage 1: x-interp into tmp[h][q] ----
        {
            int metax = __ldg(&g_meta[mbase + 7 + qx]);
            int offx = metax & 0xFF;
            const float* wpx = wbase + (7 + qx) * 12;
            #define CS1(K) case K: s1loop<K>(fmb, tmpw, ylo, span4, hsub, qx, act1, offx, wpx); break;
            switch (kx) {
                CS1(1) CS1(2) CS1(3) CS1(4) CS1(5)
                CS1(6) CS1(7) CS1(8) CS1(9)
                default: s1loop<10>(fmb, tmpw, ylo, span4, hsub, qx, act1, offx, wpx); break;
            }
            #undef CS1
        }
        __syncwarp();

        // ---- stage 2: y-interp from tmp ----
        {
            int meta0 = __ldg(&g_meta[mbase + p0]);
            int meta1 = has1 ? __ldg(&g_meta[mbase + p1]) : meta0;
            int base0 = ((meta0 & 0xFF) - ylo) * 7 + q0;
            int base1 = ((meta1 & 0xFF) - ylo) * 7 + q1;
            const float* wp0 = wbase + p0 * 12;
            const float* wp1 = wbase + p1 * 12;

            u64 s001, s023, s101, s123;
            #define CS2(K) case K: { s2cell<K>(tb, base0, wp0, s001, s023); \
                                     s2cell<K>(tb, base1, wp1, s101, s123); } break;
            switch (ky) {
                CS2(1) CS2(2) CS2(3) CS2(4) CS2(5)
                CS2(6) CS2(7) CS2(8) CS2(9)
                default: { s2cell<10>(tb, base0, wp0, s001, s023);
                           s2cell<10>(tb, base1, wp1, s101, s123); } break;
            }
            #undef CS2
            fma2(acc001, wroi2, s001);
            fma2(acc023, wroi2, s023);
            fma2(acc101, wroi2, s101);
            fma2(acc123, wroi2, s123);
        }
        __syncwarp();   // tmp reuse safety before next roi
    }

    // ---- combine: exactly 2 atomicAdd per output cell (deterministic) ----
    float* o = out + ((size_t)(b * NN + n) * CC + c0) * (PP * PP);
    {
        float2 v01 = up2(acc001), v23 = up2(acc023);
        atomicAdd(&o[lane],        v01.x);
        atomicAdd(&o[49 + lane],   v01.y);
        atomicAdd(&o[98 + lane],   v23.x);
        atomicAdd(&o[147 + lane],  v23.y);
    }
    if (has1) {
        float2 v01 = up2(acc101), v23 = up2(acc123);
        atomicAdd(&o[lane + 32],        v01.x);
        atomicAdd(&o[49 + lane + 32],   v01.y);
        atomicAdd(&o[98 + lane + 32],   v23.x);
        atomicAdd(&o[147 + lane + 32],  v23.y);
    }
}

// ---------------------------------------------------------------------------
extern "C" void kernel_launch(void* const* d_in, const int* in_sizes, int n_in,
                              void* d_out, int out_size) {
    const float* fm    = (const float*)d_in[0];
    const float* boxes = (const float*)d_in[1];
    const float* gts   = (const float*)d_in[2];
    float* out = (float*)d_out;

    // out = 2*64*256*49 = 1,605,632 floats = 401,408 float4 = 1568 * 256
    zero_out_kernel<<<1568, 256>>>((float4*)out);
    prep_kernel<<<(R_TOTAL * 2 + 127) / 128, 128>>>(boxes, gts);

    dim3 grid(CC / 4, BB, 16);   // z = (nchunk << 1) | jhalf
    roi_main_kernel<<<grid, 256>>>(fm, out);
}

// round 13
// speedup vs baseline: 1.8048x; 1.0260x over previous
#include <cuda_runtime.h>
#include <cuda_bf16.h>
#include <cuda_fp16.h>

// Problem constants (fixed by dataset)
#define BB 2
#define CC 256
#define HH 56
#define WW 56
#define NN 64
#define MM 8
#define PP 7
#define R_PER_IMG (NN + NN*MM)        // 576
#define R_TOTAL   (BB * R_PER_IMG)    // 1152
#define MAXK 12
#define KCAP 10                       // true max support count

#define FS      71                    // fm smem row stride in uint2 (4ch fp16)
#define FROWB   (FS * 8)              // row stride in bytes
#define TROWS   66                    // tmp rows

// Per-roi tables.
// g_meta[r*16 + row], rows 0..6 = y (p), 7..13 = x (q). meta = off | (cnt<<8)
// g_yinfo[r] = ylo | (span4<<8)
// g_kmax[r*2 + a] = warp-uniform EXACT max cnt for axis a (1..10)
// g_wgth[(r*14+row)*12 + k] = broadcast half2 (w,w), zero-padded to 12
__device__ int      g_meta[R_TOTAL * 16];
__device__ int      g_yinfo[R_TOTAL];
__device__ int      g_kmax[R_TOTAL * 2];
__device__ __align__(16) unsigned g_wgth[R_TOTAL * 14 * MAXK];

// ---------------------------------------------------------------------------
// Kernel A: build sparse interpolation tables. Reference math exactly
// (fp32 accumulation of weights; final store rounded to broadcast half2).
// ---------------------------------------------------------------------------
__global__ void prep_kernel(const float* __restrict__ boxes,
                            const float* __restrict__ gts) {
    int t = blockIdx.x * blockDim.x + threadIdx.x;
    if (t >= R_TOTAL * 2) return;
    int r = t >> 1, a = t & 1;
    int b = r / R_PER_IMG, idx = r % R_PER_IMG;

    float x1, y1, x2, y2;
    if (idx < NN) {
        const float* bx = boxes + (b * NN + idx) * 4;
        x1 = bx[0]; y1 = bx[1]; x2 = bx[2]; y2 = bx[3];
    } else {
        int n = (idx - NN) >> 3, m = (idx - NN) & 7;
        const float* bx = boxes + (b * NN + n) * 4;
        const float* gx = gts   + (b * MM + m) * 4;
        x1 = fminf(bx[0], gx[0]); y1 = fminf(bx[1], gx[1]);
        x2 = fmaxf(bx[2], gx[2]); y2 = fmaxf(bx[3], gx[3]);
    }

    float start = a ? x1 : y1;
    float len   = fmaxf(a ? (x2 - x1) : (y2 - y1), 1.0f);
    const float dimf = 56.0f;
    const int   dim  = 56;

    float bin = len / 7.0f;
    int   g   = (int)ceilf(bin);
    float gf  = (float)g;
    float inv = 1.0f / gf;

    int lo_min = 1 << 20, hi_max = -1, cnt_max = 1;
    for (int p = 0; p < 7; p++) {
        float acc[MAXK];
        #pragma unroll
        for (int k = 0; k < MAXK; k++) acc[k] = 0.0f;
        int base = -1, hi = -1;
        float c0 = start + (float)p * bin;
        for (int s = 0; s < 8; s++) {
            if (s >= g) break;
            float coord = c0 + ((float)s + 0.5f) * bin / gf;
            if (!(coord >= -1.0f && coord <= dimf)) continue;
            float c = fmaxf(coord, 0.0f);
            int low = (int)floorf(c);
            int high; float cv;
            if (low >= dim - 1) { low = dim - 1; high = dim - 1; cv = (float)low; }
            else                { high = low + 1; cv = c; }
            float l  = cv - (float)low;
            float wl = (1.0f - l) * inv;
            float wh = l * inv;
            if (base < 0) base = low;
            int d  = low  - base;
            int d2 = high - base;
            if (d  >= 0 && d  < MAXK) acc[d]  += wl;
            if (d2 >= 0 && d2 < MAXK) acc[d2] += wh;
            if (high > hi) hi = high;
        }
        int cnt = (base < 0) ? 0 : (hi - base + 1);
        if (base < 0) base = 0;
        if (cnt > KCAP) cnt = KCAP;
        if (base < lo_min) lo_min = base;
        if (base + cnt > hi_max) hi_max = base + cnt;
        if (cnt > cnt_max) cnt_max = cnt;
        g_meta[r * 16 + a * 7 + p] = base | (cnt << 8);
        unsigned* wp = g_wgth + (size_t)((r * 14 + a * 7 + p)) * MAXK;
        #pragma unroll
        for (int k = 0; k < MAXK; k++) {
            unsigned hb = __half_as_ushort(__float2half_rn(acc[k]));
            wp[k] = hb * 0x10001u;        // broadcast half2 (w, w)
        }
    }
    if (cnt_max < 1)    cnt_max = 1;
    if (cnt_max > KCAP) cnt_max = KCAP;
    g_kmax[r * 2 + a] = cnt_max;
    if (a == 0) {
        int lo = lo_min, span = hi_max - lo_min;
        if (span < 1) { lo = 0; span = 1; }
        int span4 = (span + 3) & ~3;
        g_yinfo[r] = lo | (span4 << 8);
    }
}

// ---------------------------------------------------------------------------
// Helpers
// ---------------------------------------------------------------------------
__device__ __forceinline__ __half2 u2h(unsigned u) {
    return *reinterpret_cast<__half2*>(&u);
}
__device__ __forceinline__ unsigned h2u(__half2 h) {
    return *reinterpret_cast<unsigned*>(&h);
}
__device__ __forceinline__ unsigned ucomp(uint4 v, int i) {
    return i == 0 ? v.x : i == 1 ? v.y : i == 2 ? v.z : v.w;
}
__device__ __forceinline__ uint2 pack4h(float a, float b, float c, float d) {
    __half2 h01 = __floats2half2_rn(a, b);
    __half2 h23 = __floats2half2_rn(c, d);
    uint2 r;
    r.x = h2u(h01);
    r.y = h2u(h23);
    return r;
}

// ---------------------------------------------------------------------------
// Stage bodies. Masking entirely via zero-padded fp16 WEIGHTS over zeroed /
// finite pad data -> plain LDS with immediate offsets, no selects.
// Within-roi accumulation in half2 (HFMA2): 3 instr per 4-channel tap.
// KM = exact warp-uniform max cnt (<=10).
// ---------------------------------------------------------------------------
template<int KM>
__device__ __forceinline__ void s1loop(const char* fmb, uint2* tmpw,
        int ylo, int span4, int hsub, int qx, bool act1,
        int offu, const unsigned* wph) {
    const uint4* w4 = (const uint4*)wph;
    uint4 wa = __ldg(w4);
    uint4 wb = (KM > 4) ? __ldg(w4 + 1) : make_uint4(0u, 0u, 0u, 0u);
    uint4 wc = (KM > 8) ? __ldg(w4 + 2) : make_uint4(0u, 0u, 0u, 0u);
    #pragma unroll 1
    for (int hb = 0; hb < span4; hb += 4) {
        if (act1) {
            int h = hb + hsub;
            const uint2* row = (const uint2*)(fmb + (ylo + h) * FROWB) + offu;
            __half2 a01 = u2h(0u), a23 = u2h(0u);
            #pragma unroll
            for (int k = 0; k < KM; k++) {
                unsigned wk = (k < 4) ? ucomp(wa, k)
                             : (k < 8) ? ucomp(wb, k - 4) : ucomp(wc, k - 8);
                uint2 hv = row[k];
                a01 = __hfma2(u2h(wk), u2h(hv.x), a01);
                a23 = __hfma2(u2h(wk), u2h(hv.y), a23);
            }
            tmpw[h * 7 + qx] = make_uint2(h2u(a01), h2u(a23));
        }
    }
}

template<int KM>
__device__ __forceinline__ void s2cell(const char* tb, int basei,
        const unsigned* wph, float2& s01, float2& s23) {
    const uint4* w4 = (const uint4*)wph;
    uint4 ua = __ldg(w4);
    uint4 ub = (KM > 4) ? __ldg(w4 + 1) : make_uint4(0u, 0u, 0u, 0u);
    uint4 uc = (KM > 8) ? __ldg(w4 + 2) : make_uint4(0u, 0u, 0u, 0u);
    __half2 h01 = u2h(0u), h23 = u2h(0u);
    #pragma unroll
    for (int k = 0; k < KM; k++) {
        unsigned wk = (k < 4) ? ucomp(ua, k)
                     : (k < 8) ? ucomp(ub, k - 4) : ucomp(uc, k - 8);
        uint2 tv = *(const uint2*)(tb + (basei + k * 7) * 8);
        h01 = __hfma2(u2h(wk), u2h(tv.x), h01);
        h23 = __hfma2(u2h(wk), u2h(tv.y), h23);
    }
    s01 = __half22float2(h01);
    s23 = __half22float2(h23);
}

// ---------------------------------------------------------------------------
// Kernel B: one CTA per (channel-quad, image, n-eighth). fm 4ch fp16 packed
// in smem, pad cols/rows zeroed; tmp fp16, zero-initialized once. 8 warps,
// one n each; per n: box roi + 8 ctx rois; roi-level accumulation fp32.
// ---------------------------------------------------------------------------
__global__ void __launch_bounds__(256, 3)
roi_main_kernel(const float* __restrict__ fm, float* __restrict__ out) {
    const int cq = blockIdx.x;               // channel quad: c0 = 4*cq
    const int b  = blockIdx.y;
    const int nbase = blockIdx.z * 8;        // 8 n per CTA, one per warp

    __shared__ uint2 fm_s[60 * FS];          // 34080 B
    __shared__ uint2 tmp_s[8][TROWS * 7];    // 29568 B

    const int tid = threadIdx.x;
    const int c0 = cq * 4;

    // ---- stage fm[b][c0..c0+3] packed fp16; zero ALL pad regions + tmp ----
    {
        const uint2 z2 = make_uint2(0u, 0u);
        for (int i = tid; i < 4 * FS; i += 256) fm_s[56 * FS + i] = z2;   // rows 56..59
        for (int i = tid; i < 56 * 15; i += 256) {                        // cols 56..70
            int h = i / 15, w = 56 + (i % 15);
            fm_s[h * FS + w] = z2;
        }
        uint2* tz = &tmp_s[0][0];
        for (int i = tid; i < 8 * TROWS * 7; i += 256) tz[i] = z2;        // tmp finite

        const float4* s0 = (const float4*)(fm + ((size_t)(b * CC + c0)     ) * (HH * WW));
        const float4* s1 = (const float4*)(fm + ((size_t)(b * CC + c0 + 1)) * (HH * WW));
        const float4* s2 = (const float4*)(fm + ((size_t)(b * CC + c0 + 2)) * (HH * WW));
        const float4* s3 = (const float4*)(fm + ((size_t)(b * CC + c0 + 3)) * (HH * WW));
        for (int i = tid; i < 784; i += 256) {
            float4 v0 = s0[i];
            float4 v1 = s1[i];
            float4 v2 = s2[i];
            float4 v3 = s3[i];
            int h = i / 14, w = (i % 14) * 4;
            uint2* d = &fm_s[h * FS + w];
            d[0] = pack4h(v0.x, v1.x, v2.x, v3.x);
            d[1] = pack4h(v0.y, v1.y, v2.y, v3.y);
            d[2] = pack4h(v0.z, v1.z, v2.z, v3.z);
            d[3] = pack4h(v0.w, v1.w, v2.w, v3.w);
        }
    }
    __syncthreads();

    const int wid  = tid >> 5;
    const int lane = tid & 31;
    uint2* tmpw = tmp_s[wid];
    const char* tb  = (const char*)tmpw;
    const char* fmb = (const char*)fm_s;

    // stage-1 lane mapping: lanes 0..27 -> (hsub, qx)
    const int qx   = lane % 7;
    const int hsub = lane / 7;
    const bool act1 = (lane < 28);

    // stage-2 cell mapping: cell0 = lane, cell1 = lane+32
    const int p0 = lane / 7,        q0 = lane % 7;
    const int p1 = (lane + 32) / 7, q1 = (lane + 32) % 7;
    const bool has1 = (lane + 32 < 49);

    const int n = nbase + wid;

    float4 acc0 = make_float4(0.f, 0.f, 0.f, 0.f);
    float4 acc1 = make_float4(0.f, 0.f, 0.f, 0.f);

    #pragma unroll 1
    for (int j = 0; j < 9; j++) {
        const int r = b * R_PER_IMG + ((j == 0) ? n : (NN + n * 8 + (j - 1)));
        const float wroi = (j == 0) ? 1.0f : 0.125f;
        const int yinfo = __ldg(&g_yinfo[r]);
        const int ylo   = yinfo & 0xFF;
        const int span4 = yinfo >> 8;
        const int ky    = __ldg(&g_kmax[r * 2]);
        const int kx    = __ldg(&g_kmax[r * 2 + 1]);
        const int mbase = r * 16;
        const unsigned* whbase = g_wgth + (size_t)r * 168;

        // ---- stage 1: x-interp into tmp[h][q] (fp16 accum) ----
        {
            int metax = __ldg(&g_meta[mbase + 7 + qx]);
            int offx = metax & 0xFF;
            const unsigned* wpx = whbase + (7 + qx) * 12;
            #define CS1(K) case K: s1loop<K>(fmb, tmpw, ylo, span4, hsub, qx, act1, offx, wpx); break;
            switch (kx) {
                CS1(1) CS1(2) CS1(3) CS1(4) CS1(5)
                CS1(6) CS1(7) CS1(8) CS1(9)
                default: s1loop<10>(fmb, tmpw, ylo, span4, hsub, qx, act1, offx, wpx); break;
            }
            #undef CS1
        }
        __syncwarp();

        // ---- stage 2: y-interp from tmp (fp16 accum, fp32 roi combine) ----
        {
            int meta0 = __ldg(&g_meta[mbase + p0]);
            int meta1 = has1 ? __ldg(&g_meta[mbase + p1]) : meta0;
            int base0 = ((meta0 & 0xFF) - ylo) * 7 + q0;
            int base1 = ((meta1 & 0xFF) - ylo) * 7 + q1;
            const unsigned* wp0 = whbase + p0 * 12;
            const unsigned* wp1 = whbase + p1 * 12;

            float2 s001, s023, s101, s123;
            #define CS2(K) case K: { s2cell<K>(tb, base0, wp0, s001, s023); \
                                     s2cell<K>(tb, base1, wp1, s101, s123); } break;
            switch (ky) {
                CS2(1) CS2(2) CS2(3) CS2(4) CS2(5)
                CS2(6) CS2(7) CS2(8) CS2(9)
                default: { s2cell<10>(tb, base0, wp0, s001, s023);
                           s2cell<10>(tb, base1, wp1, s101, s123); } break;
            }
            #undef CS2
            acc0.x += wroi * s001.x; acc0.y += wroi * s001.y;
            acc0.z += wroi * s023.x; acc0.w += wroi * s023.y;
            acc1.x += wroi * s101.x; acc1.y += wroi * s101.y;
            acc1.z += wroi * s123.x; acc1.w += wroi * s123.y;
        }
        __syncwarp();   // tmp reuse safety before next roi
    }

    // ---- store out[b][n][c][p][q], channels c0..c0+3 ----
    float* o = out + ((size_t)(b * NN + n) * CC + c0) * (PP * PP);
    o[lane]       = acc0.x;
    o[49 + lane]  = acc0.y;
    o[98 + lane]  = acc0.z;
    o[147 + lane] = acc0.w;
    if (has1) {
        o[lane + 32]       = acc1.x;
        o[49 + lane + 32]  = acc1.y;
        o[98 + lane + 32]  = acc1.z;
        o[147 + lane + 32] = acc1.w;
    }
}

// ---------------------------------------------------------------------------
extern "C" void kernel_launch(void* const* d_in, const int* in_sizes, int n_in,
                              void* d_out, int out_size) {
    const float* fm    = (const float*)d_in[0];
    const float* boxes = (const float*)d_in[1];
    const float* gts   = (const float*)d_in[2];
    float* out = (float*)d_out;

    prep_kernel<<<(R_TOTAL * 2 + 127) / 128, 128>>>(boxes, gts);

    dim3 grid(CC / 4, BB, 8);
    roi_main_kernel<<<grid, 256>>>(fm, out);
}